// round 8
// baseline (speedup 1.0000x reference)
#include <cuda_runtime.h>
#include <cuda_bf16.h>
#include <math.h>

// ---------------------------------------------------------------------------
// CrossModalAttention, round 8:
//  - presplit fused into one launch
//  - gemm_split / gemm_fast with ldsm_x4 B fragments
//  - attention split into two lean kernels (register-pressure relief):
//      pass1: QK bf16 + exp2 + rowsum -> g_inv, PV register reuse, ctx
//      pass2: split-precision QK (3 MMA) + exp2*inv -> attn
// ---------------------------------------------------------------------------

#define HIDDEN 1024
#define HEADS  16
#define DH     64
#define NBATCH 2
#define SEQ    2048
#define MROWS  (NBATCH * SEQ)   // 4096
#define LN_EPS 1e-5f
#define LOG2E  1.44269504088896f

__device__ __nv_bfloat16 g_Wqh[HIDDEN * HIDDEN], g_Wql[HIDDEN * HIDDEN];
__device__ __nv_bfloat16 g_Wkh[HIDDEN * HIDDEN], g_Wkl[HIDDEN * HIDDEN];
__device__ __nv_bfloat16 g_Wvh[HIDDEN * HIDDEN], g_Woh[HIDDEN * HIDDEN];
__device__ __nv_bfloat16 g_Xqh[MROWS * HIDDEN], g_Xql[MROWS * HIDDEN];
__device__ __nv_bfloat16 g_Xkh[MROWS * HIDDEN], g_Xkl[MROWS * HIDDEN];
__device__ __nv_bfloat16 g_Xvh[MROWS * HIDDEN];
__device__ __nv_bfloat16 g_Qh[MROWS * HIDDEN], g_Ql[MROWS * HIDDEN];
__device__ __nv_bfloat16 g_Kh[MROWS * HIDDEN], g_Kl[MROWS * HIDDEN];
__device__ __nv_bfloat16 g_Vh[MROWS * HIDDEN];
__device__ __nv_bfloat16 g_ctx[MROWS * HIDDEN];
__device__ float g_proj[MROWS * HIDDEN];
__device__ float g_inv[NBATCH * HEADS * SEQ];

// ---------------------------------------------------------------------------
// PTX helpers
// ---------------------------------------------------------------------------
__device__ __forceinline__ void mma_bf16(float* c, const unsigned* a, const unsigned* b) {
    asm volatile(
        "mma.sync.aligned.m16n8k16.row.col.f32.bf16.bf16.f32 "
        "{%0,%1,%2,%3}, {%4,%5,%6,%7}, {%8,%9}, {%0,%1,%2,%3};\n"
        : "+f"(c[0]), "+f"(c[1]), "+f"(c[2]), "+f"(c[3])
        : "r"(a[0]), "r"(a[1]), "r"(a[2]), "r"(a[3]), "r"(b[0]), "r"(b[1]));
}
__device__ __forceinline__ void ldsm_x4(unsigned* r, const __nv_bfloat16* p) {
    unsigned a = (unsigned)__cvta_generic_to_shared(p);
    asm volatile("ldmatrix.sync.aligned.m8n8.x4.shared.b16 {%0,%1,%2,%3}, [%4];\n"
                 : "=r"(r[0]), "=r"(r[1]), "=r"(r[2]), "=r"(r[3]) : "r"(a));
}
__device__ __forceinline__ void ldsm_x4t(unsigned* r, const __nv_bfloat16* p) {
    unsigned a = (unsigned)__cvta_generic_to_shared(p);
    asm volatile("ldmatrix.sync.aligned.m8n8.x4.trans.shared.b16 {%0,%1,%2,%3}, [%4];\n"
                 : "=r"(r[0]), "=r"(r[1]), "=r"(r[2]), "=r"(r[3]) : "r"(a));
}
#define CP_ASYNC16(dst, src) \
    asm volatile("cp.async.cg.shared.global [%0], [%1], 16;\n" :: "r"(dst), "l"(src))
#define CP_COMMIT() asm volatile("cp.async.commit_group;\n")
#define CP_WAIT(n)  asm volatile("cp.async.wait_group %0;\n" :: "n"(n))

__device__ __forceinline__ unsigned pack_bf2(float x, float y) {
    __nv_bfloat162 h = __float22bfloat162_rn(make_float2(x, y));
    return *(unsigned*)&h;
}
__device__ __forceinline__ void split_pair(float x, float y,
                                           __nv_bfloat162& hi, __nv_bfloat162& lo) {
    hi = __float22bfloat162_rn(make_float2(x, y));
    float2 hf = __bfloat1622float2(hi);
    lo = __float22bfloat162_rn(make_float2(x - hf.x, y - hf.y));
}

// ---------------------------------------------------------------------------
// presplit: z = 0..6 selects tensor (fused single launch)
// ---------------------------------------------------------------------------
#define W4 (HIDDEN * HIDDEN / 4)
#define X4 (MROWS * HIDDEN / 4)

__global__ void presplit_all(
    const float* __restrict__ Wq, const float* __restrict__ Wk,
    const float* __restrict__ q,  const float* __restrict__ k,
    const float* __restrict__ Wv, const float* __restrict__ Wo,
    const float* __restrict__ v,
    __nv_bfloat16* __restrict__ Wqh, __nv_bfloat16* __restrict__ Wql,
    __nv_bfloat16* __restrict__ Wkh, __nv_bfloat16* __restrict__ Wkl,
    __nv_bfloat16* __restrict__ Xqh, __nv_bfloat16* __restrict__ Xql,
    __nv_bfloat16* __restrict__ Xkh, __nv_bfloat16* __restrict__ Xkl,
    __nv_bfloat16* __restrict__ Wvh, __nv_bfloat16* __restrict__ Woh,
    __nv_bfloat16* __restrict__ Xvh) {
    const int z = blockIdx.y;
    const int i = blockIdx.x * blockDim.x + threadIdx.x;
    const float* src; __nv_bfloat16 *h, *l = nullptr; int n4;
    switch (z) {
        case 0: src = Wq; h = Wqh; l = Wql; n4 = W4; break;
        case 1: src = Wk; h = Wkh; l = Wkl; n4 = W4; break;
        case 2: src = q;  h = Xqh; l = Xql; n4 = X4; break;
        case 3: src = k;  h = Xkh; l = Xkl; n4 = X4; break;
        case 4: src = Wv; h = Wvh; n4 = W4; break;
        case 5: src = Wo; h = Woh; n4 = W4; break;
        default: src = v; h = Xvh; n4 = X4; break;
    }
    if (i >= n4) return;
    float4 val = ((const float4*)src)[i];
    if (l) {
        __nv_bfloat162 h0, l0, h1, l1;
        split_pair(val.x, val.y, h0, l0);
        split_pair(val.z, val.w, h1, l1);
        ((__nv_bfloat162*)h)[2 * i]     = h0;
        ((__nv_bfloat162*)h)[2 * i + 1] = h1;
        ((__nv_bfloat162*)l)[2 * i]     = l0;
        ((__nv_bfloat162*)l)[2 * i + 1] = l1;
    } else {
        ((__nv_bfloat162*)h)[2 * i]     = __float22bfloat162_rn(make_float2(val.x, val.y));
        ((__nv_bfloat162*)h)[2 * i + 1] = __float22bfloat162_rn(make_float2(val.z, val.w));
    }
}

// ---------------------------------------------------------------------------
// staging helper: 128 rows x 32 bf16 (row stride 40) via cp.async, 256 thr
// ---------------------------------------------------------------------------
__device__ __forceinline__ void stage_tile(unsigned smbase, const __nv_bfloat16* g, int t) {
#pragma unroll
    for (int r = 0; r < 2; ++r) {
        int idx = t + r * 256;
        int row = idx >> 2;
        int c8  = (idx & 3) * 8;
        CP_ASYNC16(smbase + (unsigned)(row * 40 + c8) * 2, g + (size_t)row * HIDDEN + c8);
    }
}

// B fragments: 4 n8-tiles x k16 via 2 ldsm_x4
__device__ __forceinline__ void load_bfrag(unsigned bf[4][2], const __nv_bfloat16* B,
                                           int wn, int ks, int lane) {
#pragma unroll
    for (int jj = 0; jj < 2; ++jj) {
        unsigned r[4];
        int br = wn * 32 + jj * 16 + (lane & 15);
        int bc = ks + ((lane & 16) ? 8 : 0);
        ldsm_x4(r, &B[br * 40 + bc]);
        bf[2 * jj][0] = r[0]; bf[2 * jj][1] = r[2];
        bf[2 * jj + 1][0] = r[1]; bf[2 * jj + 1][1] = r[3];
    }
}

// ---------------------------------------------------------------------------
// gemm_split: C = (Ah+Al)(Wh+Wl)^T + bias (3-MMA), bf16 hi/lo out.
// ---------------------------------------------------------------------------
#define GS_STAGE 10240
#define GS_SMEM  (8 * GS_STAGE)

__global__ __launch_bounds__(256) void gemm_split_kernel(
    const __nv_bfloat16* __restrict__ Ahg, const __nv_bfloat16* __restrict__ Alg,
    const __nv_bfloat16* __restrict__ Whg, const __nv_bfloat16* __restrict__ Wlg,
    const float* __restrict__ bias,
    __nv_bfloat16* __restrict__ OH, __nv_bfloat16* __restrict__ OL) {
    extern __shared__ __align__(16) char sm[];
    const unsigned sb = (unsigned)__cvta_generic_to_shared(sm);

    const int t = threadIdx.x, lane = t & 31, warp = t >> 5;
    const int wm = warp >> 2, wn = warp & 3;
    const int m0 = blockIdx.y * 128, n0 = blockIdx.x * 128;

    const __nv_bfloat16* Ah0 = Ahg + (size_t)m0 * HIDDEN;
    const __nv_bfloat16* Al0 = Alg + (size_t)m0 * HIDDEN;
    const __nv_bfloat16* Wh0 = Whg + (size_t)n0 * HIDDEN;
    const __nv_bfloat16* Wl0 = Wlg + (size_t)n0 * HIDDEN;

    float acc[4][4][4] = {};

    stage_tile(sb + 0 * GS_STAGE, Ah0, t);
    stage_tile(sb + 1 * GS_STAGE, Al0, t);
    stage_tile(sb + 2 * GS_STAGE, Wh0, t);
    stage_tile(sb + 3 * GS_STAGE, Wl0, t);
    CP_COMMIT();

    for (int i = 0; i < 32; ++i) {
        if (i < 31) {
            int k1 = (i + 1) * 32;
            unsigned s1 = sb + ((i + 1) & 1) * 4 * GS_STAGE;
            stage_tile(s1 + 0 * GS_STAGE, Ah0 + k1, t);
            stage_tile(s1 + 1 * GS_STAGE, Al0 + k1, t);
            stage_tile(s1 + 2 * GS_STAGE, Wh0 + k1, t);
            stage_tile(s1 + 3 * GS_STAGE, Wl0 + k1, t);
            CP_COMMIT();
            CP_WAIT(1);
        } else {
            CP_WAIT(0);
        }
        __syncthreads();

        char* base = sm + (i & 1) * 4 * GS_STAGE;
        const __nv_bfloat16* Ah = (const __nv_bfloat16*)(base);
        const __nv_bfloat16* Al = (const __nv_bfloat16*)(base + GS_STAGE);
        const __nv_bfloat16* Bh = (const __nv_bfloat16*)(base + 2 * GS_STAGE);
        const __nv_bfloat16* Bl = (const __nv_bfloat16*)(base + 3 * GS_STAGE);

#pragma unroll
        for (int ks = 0; ks < 32; ks += 16) {
            unsigned ah[4][4], al[4][4], bhf[4][2], blf[4][2];
            load_bfrag(bhf, Bh, wn, ks, lane);
            load_bfrag(blf, Bl, wn, ks, lane);
#pragma unroll
            for (int ii = 0; ii < 4; ++ii) {
                int ar = wm * 64 + ii * 16 + (lane & 15);
                int ac = ks + ((lane & 16) ? 8 : 0);
                ldsm_x4(ah[ii], &Ah[ar * 40 + ac]);
                ldsm_x4(al[ii], &Al[ar * 40 + ac]);
            }
#pragma unroll
            for (int ii = 0; ii < 4; ++ii)
#pragma unroll
                for (int j = 0; j < 4; ++j) {
                    mma_bf16(acc[ii][j], ah[ii], bhf[j]);
                    mma_bf16(acc[ii][j], ah[ii], blf[j]);
                    mma_bf16(acc[ii][j], al[ii], bhf[j]);
                }
        }
        __syncthreads();
    }

    const int g = lane >> 2, t2 = (lane & 3) * 2;
#pragma unroll
    for (int i = 0; i < 4; ++i) {
        int row = m0 + wm * 64 + i * 16 + g;
#pragma unroll
        for (int j = 0; j < 4; ++j) {
            int col = n0 + wn * 32 + j * 8 + t2;
            float bb0 = bias[col], bb1 = bias[col + 1];
            __nv_bfloat162 h2, l2;
            split_pair(acc[i][j][0] + bb0, acc[i][j][1] + bb1, h2, l2);
            *(__nv_bfloat162*)&OH[(size_t)row * HIDDEN + col] = h2;
            *(__nv_bfloat162*)&OL[(size_t)row * HIDDEN + col] = l2;
            split_pair(acc[i][j][2] + bb0, acc[i][j][3] + bb1, h2, l2);
            *(__nv_bfloat162*)&OH[(size_t)(row + 8) * HIDDEN + col] = h2;
            *(__nv_bfloat162*)&OL[(size_t)(row + 8) * HIDDEN + col] = l2;
        }
    }
}

// ---------------------------------------------------------------------------
// gemm_fast: C = A W^T + bias (1 MMA), bf16 or fp32 out.
// ---------------------------------------------------------------------------
__global__ __launch_bounds__(256) void gemm_fast_kernel(
    const __nv_bfloat16* __restrict__ Ahg, const __nv_bfloat16* __restrict__ Whg,
    const float* __restrict__ bias,
    __nv_bfloat16* __restrict__ Obf, float* __restrict__ Of) {
    __shared__ __align__(16) __nv_bfloat16 smf[2][2][128 * 40];
    const int t = threadIdx.x, lane = t & 31, warp = t >> 5;
    const int wm = warp >> 2, wn = warp & 3;
    const int m0 = blockIdx.y * 128, n0 = blockIdx.x * 128;

    const __nv_bfloat16* A0 = Ahg + (size_t)m0 * HIDDEN;
    const __nv_bfloat16* W0 = Whg + (size_t)n0 * HIDDEN;

    float acc[4][4][4] = {};

    stage_tile((unsigned)__cvta_generic_to_shared(smf[0][0]), A0, t);
    stage_tile((unsigned)__cvta_generic_to_shared(smf[0][1]), W0, t);
    CP_COMMIT();

    for (int i = 0; i < 32; ++i) {
        if (i < 31) {
            int k1 = (i + 1) * 32;
            int s = (i + 1) & 1;
            stage_tile((unsigned)__cvta_generic_to_shared(smf[s][0]), A0 + k1, t);
            stage_tile((unsigned)__cvta_generic_to_shared(smf[s][1]), W0 + k1, t);
            CP_COMMIT();
            CP_WAIT(1);
        } else {
            CP_WAIT(0);
        }
        __syncthreads();

        const __nv_bfloat16* Ah = smf[i & 1][0];
        const __nv_bfloat16* Bh = smf[i & 1][1];

#pragma unroll
        for (int ks = 0; ks < 32; ks += 16) {
            unsigned ah[4][4], bhf[4][2];
            load_bfrag(bhf, Bh, wn, ks, lane);
#pragma unroll
            for (int ii = 0; ii < 4; ++ii) {
                int ar = wm * 64 + ii * 16 + (lane & 15);
                int ac = ks + ((lane & 16) ? 8 : 0);
                ldsm_x4(ah[ii], &Ah[ar * 40 + ac]);
            }
#pragma unroll
            for (int ii = 0; ii < 4; ++ii)
#pragma unroll
                for (int j = 0; j < 4; ++j)
                    mma_bf16(acc[ii][j], ah[ii], bhf[j]);
        }
        __syncthreads();
    }

    const int g = lane >> 2, t2 = (lane & 3) * 2;
    if (Of) {
#pragma unroll
        for (int i = 0; i < 4; ++i) {
            int row = m0 + wm * 64 + i * 16 + g;
#pragma unroll
            for (int j = 0; j < 4; ++j) {
                int col = n0 + wn * 32 + j * 8 + t2;
                float bb0 = bias[col], bb1 = bias[col + 1];
                *(float2*)&Of[(size_t)row * HIDDEN + col] =
                    make_float2(acc[i][j][0] + bb0, acc[i][j][1] + bb1);
                *(float2*)&Of[(size_t)(row + 8) * HIDDEN + col] =
                    make_float2(acc[i][j][2] + bb0, acc[i][j][3] + bb1);
            }
        }
    } else {
#pragma unroll
        for (int i = 0; i < 4; ++i) {
            int row = m0 + wm * 64 + i * 16 + g;
#pragma unroll
            for (int j = 0; j < 4; ++j) {
                int col = n0 + wn * 32 + j * 8 + t2;
                float bb0 = bias[col], bb1 = bias[col + 1];
                *(__nv_bfloat162*)&Obf[(size_t)row * HIDDEN + col] =
                    __float22bfloat162_rn(make_float2(acc[i][j][0] + bb0, acc[i][j][1] + bb1));
                *(__nv_bfloat162*)&Obf[(size_t)(row + 8) * HIDDEN + col] =
                    __float22bfloat162_rn(make_float2(acc[i][j][2] + bb0, acc[i][j][3] + bb1));
            }
        }
    }
}

// ---------------------------------------------------------------------------
// attn staging: 128 rows x 64 bf16 cols (stride 72), 512 threads
// ---------------------------------------------------------------------------
__device__ __forceinline__ void stage512(unsigned sm, const __nv_bfloat16* g, int t) {
#pragma unroll
    for (int r = 0; r < 2; ++r) {
        int idx = t + r * 512;
        int row = idx >> 3;
        int c8  = (idx & 7) * 8;
        CP_ASYNC16(sm + (unsigned)(row * 72 + c8) * 2, g + (size_t)row * HIDDEN + c8);
    }
}

// ---------------------------------------------------------------------------
// attn pass 1: QK bf16 + exp2 + rowsum (-> g_inv) + PV register reuse -> ctx
// smem: QH 0(18432), K 18432(2x18432), V 55296(2x18432, reused as red),
//       part 92160(1024), inv 93184(512) -> 93696
// ---------------------------------------------------------------------------
#define P1_QH 0
#define P1_K  18432
#define P1_V  55296
#define P1_PART 92160
#define P1_INV  93184
#define P1_SMEM 93696

__global__ __launch_bounds__(512) void attn_pass1_kernel(
    const __nv_bfloat16* __restrict__ Qh,
    const __nv_bfloat16* __restrict__ Kh,
    const __nv_bfloat16* __restrict__ Vh,
    const float* __restrict__ temp,
    float* __restrict__ inv_out, __nv_bfloat16* __restrict__ ctx) {
    extern __shared__ __align__(16) char smraw[];
    __nv_bfloat16* q_h = (__nv_bfloat16*)(smraw + P1_QH);
    float* red    = (float*)(smraw + P1_V);
    float* part   = (float*)(smraw + P1_PART);
    float* sm_inv = (float*)(smraw + P1_INV);
    const unsigned sb = (unsigned)__cvta_generic_to_shared(smraw);

    const int t = threadIdx.x, lane = t & 31, wid = t >> 5;
    const int wm = wid >> 1, wn = wid & 1;
    const int bh = blockIdx.y, b = bh >> 4, h = bh & 15;
    const int q0 = blockIdx.x * 128;
    const float tsl = temp[0] * LOG2E;
    const int g = lane >> 2, t2 = (lane & 3) * 2;
    const int lr = lane & 15, hc = (lane & 16) ? 8 : 0;

    const size_t qoff = (size_t)(b * SEQ + q0) * HIDDEN + h * DH;
    const size_t koff = (size_t)(b * SEQ) * HIDDEN + h * DH;

    stage512(sb + P1_QH, Qh + qoff, t);
    CP_COMMIT();
    stage512(sb + P1_K, Kh + koff, t);
    stage512(sb + P1_V, Vh + koff, t);
    CP_COMMIT();

    CP_WAIT(1);
    __syncthreads();
    unsigned aqh_f[4][4];
#pragma unroll
    for (int kd = 0; kd < 4; ++kd)
        ldsm_x4(aqh_f[kd], &q_h[(wm * 16 + lr) * 72 + kd * 16 + hc]);

    float acc[8][4] = {};
    float rs0 = 0.f, rs1 = 0.f;

    for (int kt = 0; kt < 16; ++kt) {
        __syncthreads();
        if (kt < 15) {
            size_t go = (size_t)(kt + 1) * 128 * HIDDEN;
            stage512(sb + P1_K + ((kt + 1) & 1) * 18432, Kh + koff + go, t);
            stage512(sb + P1_V + ((kt + 1) & 1) * 18432, Vh + koff + go, t);
            CP_COMMIT();
            CP_WAIT(1);
        } else {
            CP_WAIT(0);
        }
        __syncthreads();

        const __nv_bfloat16* k_h = (const __nv_bfloat16*)(smraw + P1_K + (kt & 1) * 18432);
        const __nv_bfloat16* v_h = (const __nv_bfloat16*)(smraw + P1_V + (kt & 1) * 18432);

        float c[8][4] = {};
#pragma unroll
        for (int kd = 0; kd < 4; ++kd) {
#pragma unroll
            for (int jp = 0; jp < 4; ++jp) {
                unsigned bb[4];
                ldsm_x4(bb, &k_h[(wn * 64 + jp * 16 + lr) * 72 + kd * 16 + hc]);
                unsigned be[2] = {bb[0], bb[2]}, bo[2] = {bb[1], bb[3]};
                mma_bf16(c[2 * jp],     aqh_f[kd], be);
                mma_bf16(c[2 * jp + 1], aqh_f[kd], bo);
            }
        }

#pragma unroll
        for (int j = 0; j < 8; ++j) {
            c[j][0] = exp2f(c[j][0] * tsl);
            c[j][1] = exp2f(c[j][1] * tsl);
            c[j][2] = exp2f(c[j][2] * tsl);
            c[j][3] = exp2f(c[j][3] * tsl);
            rs0 += c[j][0] + c[j][1];
            rs1 += c[j][2] + c[j][3];
        }

#pragma unroll
        for (int j2 = 0; j2 < 4; ++j2) {
            unsigned ap[4];
            ap[0] = pack_bf2(c[2 * j2][0],     c[2 * j2][1]);
            ap[1] = pack_bf2(c[2 * j2][2],     c[2 * j2][3]);
            ap[2] = pack_bf2(c[2 * j2 + 1][0], c[2 * j2 + 1][1]);
            ap[3] = pack_bf2(c[2 * j2 + 1][2], c[2 * j2 + 1][3]);
#pragma unroll
            for (int djp = 0; djp < 4; ++djp) {
                unsigned bv[4];
                ldsm_x4t(bv, &v_h[(wn * 64 + j2 * 16 + lr) * 72 + djp * 16 + hc]);
                unsigned b0[2] = {bv[0], bv[1]}, b1[2] = {bv[2], bv[3]};
                mma_bf16(acc[2 * djp],     ap, b0);
                mma_bf16(acc[2 * djp + 1], ap, b1);
            }
        }
    }

    // rowsum reduce -> sm_inv + g_inv
    rs0 += __shfl_xor_sync(0xffffffffu, rs0, 1);
    rs0 += __shfl_xor_sync(0xffffffffu, rs0, 2);
    rs1 += __shfl_xor_sync(0xffffffffu, rs1, 1);
    rs1 += __shfl_xor_sync(0xffffffffu, rs1, 2);
    if ((lane & 3) == 0) {
        part[wn * 128 + wm * 16 + g]     = rs0;
        part[wn * 128 + wm * 16 + g + 8] = rs1;
    }
    __syncthreads();
    if (t < 128) {
        float iv = 1.0f / (part[t] + part[128 + t]);
        sm_inv[t] = iv;
        inv_out[(size_t)bh * SEQ + q0 + t] = iv;
    }

    // ctx reduction across wn (deterministic)
    if (wn == 0) {
#pragma unroll
        for (int dj = 0; dj < 8; ++dj) {
            int r0 = wm * 16 + g, d = dj * 8 + t2;
            red[r0 * 66 + d]           = acc[dj][0];
            red[r0 * 66 + d + 1]       = acc[dj][1];
            red[(r0 + 8) * 66 + d]     = acc[dj][2];
            red[(r0 + 8) * 66 + d + 1] = acc[dj][3];
        }
    }
    __syncthreads();
    if (wn == 1) {
#pragma unroll
        for (int dj = 0; dj < 8; ++dj) {
            int r0 = wm * 16 + g, d = dj * 8 + t2;
            red[r0 * 66 + d]           += acc[dj][0];
            red[r0 * 66 + d + 1]       += acc[dj][1];
            red[(r0 + 8) * 66 + d]     += acc[dj][2];
            red[(r0 + 8) * 66 + d + 1] += acc[dj][3];
        }
    }
    __syncthreads();

    {
        int row = t >> 2, d0 = (t & 3) * 16;
        float iv = sm_inv[row];
        size_t o = (size_t)(b * SEQ + q0 + row) * HIDDEN + h * DH + d0;
#pragma unroll
        for (int u = 0; u < 8; ++u) {
            float x = red[row * 66 + d0 + 2 * u]     * iv;
            float y = red[row * 66 + d0 + 2 * u + 1] * iv;
            *(__nv_bfloat162*)&ctx[o + 2 * u] =
                __float22bfloat162_rn(make_float2(x, y));
        }
    }
}

// ---------------------------------------------------------------------------
// attn pass 2: split QK (3 MMA) + exp2*inv -> normalized attn
// smem: QH 0(18432), QL 18432(18432), K 36864 (2 stages x (hi+lo) 36864),
//       inv 110592(512) -> 111104
// ---------------------------------------------------------------------------
#define P2_QH 0
#define P2_QL 18432
#define P2_K  36864
#define P2_INV 110592
#define P2_SMEM 111104

__global__ __launch_bounds__(512) void attn_pass2_kernel(
    const __nv_bfloat16* __restrict__ Qh, const __nv_bfloat16* __restrict__ Ql,
    const __nv_bfloat16* __restrict__ Kh, const __nv_bfloat16* __restrict__ Kl,
    const float* __restrict__ temp, const float* __restrict__ inv_in,
    float* __restrict__ attn) {
    extern __shared__ __align__(16) char smraw[];
    __nv_bfloat16* q_h = (__nv_bfloat16*)(smraw + P2_QH);
    __nv_bfloat16* q_l = (__nv_bfloat16*)(smraw + P2_QL);
    float* sm_inv = (float*)(smraw + P2_INV);
    const unsigned sb = (unsigned)__cvta_generic_to_shared(smraw);

    const int t = threadIdx.x, lane = t & 31, wid = t >> 5;
    const int wm = wid >> 1, wn = wid & 1;
    const int bh = blockIdx.y, b = bh >> 4, h = bh & 15;
    const int q0 = blockIdx.x * 128;
    const float tsl = temp[0] * LOG2E;
    const int g = lane >> 2, t2 = (lane & 3) * 2;
    const int lr = lane & 15, hc = (lane & 16) ? 8 : 0;

    const size_t qoff = (size_t)(b * SEQ + q0) * HIDDEN + h * DH;
    const size_t koff = (size_t)(b * SEQ) * HIDDEN + h * DH;

    stage512(sb + P2_QH, Qh + qoff, t);
    stage512(sb + P2_QL, Ql + qoff, t);
    CP_COMMIT();
    stage512(sb + P2_K,         Kh + koff, t);
    stage512(sb + P2_K + 18432, Kl + koff, t);
    CP_COMMIT();

    if (t < 128) sm_inv[t] = inv_in[(size_t)bh * SEQ + q0 + t];

    CP_WAIT(1);
    __syncthreads();
    unsigned aqh_f[4][4], aql_f[4][4];
#pragma unroll
    for (int kd = 0; kd < 4; ++kd) {
        ldsm_x4(aqh_f[kd], &q_h[(wm * 16 + lr) * 72 + kd * 16 + hc]);
        ldsm_x4(aql_f[kd], &q_l[(wm * 16 + lr) * 72 + kd * 16 + hc]);
    }

    const int rl = wm * 16 + g;
    const float iv0 = sm_inv[rl], iv1 = sm_inv[rl + 8];

    for (int kt = 0; kt < 16; ++kt) {
        __syncthreads();
        if (kt < 15) {
            size_t go = (size_t)(kt + 1) * 128 * HIDDEN;
            unsigned kb = sb + P2_K + ((kt + 1) & 1) * 36864;
            stage512(kb,         Kh + koff + go, t);
            stage512(kb + 18432, Kl + koff + go, t);
            CP_COMMIT();
            CP_WAIT(1);
        } else {
            CP_WAIT(0);
        }
        __syncthreads();

        const __nv_bfloat16* k_h = (const __nv_bfloat16*)(smraw + P2_K + (kt & 1) * 36864);
        const __nv_bfloat16* k_l = k_h + 9216;

        float c[8][4] = {};
#pragma unroll
        for (int kd = 0; kd < 4; ++kd) {
#pragma unroll
            for (int jp = 0; jp < 4; ++jp) {
                unsigned bh4[4], bl4[4];
                ldsm_x4(bh4, &k_h[(wn * 64 + jp * 16 + lr) * 72 + kd * 16 + hc]);
                ldsm_x4(bl4, &k_l[(wn * 64 + jp * 16 + lr) * 72 + kd * 16 + hc]);
                unsigned bhe[2] = {bh4[0], bh4[2]}, bho[2] = {bh4[1], bh4[3]};
                unsigned ble[2] = {bl4[0], bl4[2]}, blo[2] = {bl4[1], bl4[3]};
                mma_bf16(c[2 * jp], aqh_f[kd], bhe);
                mma_bf16(c[2 * jp], aqh_f[kd], ble);
                mma_bf16(c[2 * jp], aql_f[kd], bhe);
                mma_bf16(c[2 * jp + 1], aqh_f[kd], bho);
                mma_bf16(c[2 * jp + 1], aqh_f[kd], blo);
                mma_bf16(c[2 * jp + 1], aql_f[kd], bho);
            }
        }

        size_t r0 = ((size_t)bh * SEQ + q0 + rl) * SEQ + (size_t)kt * 128 + wn * 64;
        size_t r1 = r0 + (size_t)8 * SEQ;
#pragma unroll
        for (int j = 0; j < 8; ++j) {
            float p0 = exp2f(c[j][0] * tsl) * iv0;
            float p1 = exp2f(c[j][1] * tsl) * iv0;
            float p2 = exp2f(c[j][2] * tsl) * iv1;
            float p3 = exp2f(c[j][3] * tsl) * iv1;
            int col = j * 8 + t2;
            *(float2*)&attn[r0 + col] = make_float2(p0, p1);
            *(float2*)&attn[r1 + col] = make_float2(p2, p3);
        }
    }
}

// ---------------------------------------------------------------------------
// LayerNorm(proj + query) -> out
// ---------------------------------------------------------------------------
__global__ void ln_kernel(const float* __restrict__ proj,
                          const float* __restrict__ query,
                          const float* __restrict__ gamma,
                          const float* __restrict__ beta,
                          float* __restrict__ out) {
    __shared__ float red[8];
    const size_t row = blockIdx.x;
    const int t = threadIdx.x;

    float x[4];
    float s = 0.f;
#pragma unroll
    for (int i = 0; i < 4; ++i) {
        int c = t + i * 256;
        x[i] = proj[row * HIDDEN + c] + query[row * HIDDEN + c];
        s += x[i];
    }
#pragma unroll
    for (int o = 16; o; o >>= 1) s += __shfl_xor_sync(0xffffffffu, s, o);
    if ((t & 31) == 0) red[t >> 5] = s;
    __syncthreads();
    s = red[0];
#pragma unroll
    for (int i = 1; i < 8; ++i) s += red[i];
    const float mu = s * (1.f / HIDDEN);

    float vs = 0.f;
#pragma unroll
    for (int i = 0; i < 4; ++i) { float d = x[i] - mu; vs += d * d; }
#pragma unroll
    for (int o = 16; o; o >>= 1) vs += __shfl_xor_sync(0xffffffffu, vs, o);
    __syncthreads();
    if ((t & 31) == 0) red[t >> 5] = vs;
    __syncthreads();
    vs = red[0];
#pragma unroll
    for (int i = 1; i < 8; ++i) vs += red[i];
    const float inv = rsqrtf(vs * (1.f / HIDDEN) + LN_EPS);

#pragma unroll
    for (int i = 0; i < 4; ++i) {
        int c = t + i * 256;
        out[row * HIDDEN + c] = (x[i] - mu) * inv * gamma[c] + beta[c];
    }
}

// ---------------------------------------------------------------------------
// Launch
// ---------------------------------------------------------------------------
extern "C" void kernel_launch(void* const* d_in, const int* in_sizes, int n_in,
                              void* d_out, int out_size) {
    const float* query = (const float*)d_in[0];
    const float* key   = (const float*)d_in[1];
    const float* value = (const float*)d_in[2];
    const float* Wq    = (const float*)d_in[3];
    const float* bq    = (const float*)d_in[4];
    const float* Wk    = (const float*)d_in[5];
    const float* bk    = (const float*)d_in[6];
    const float* Wv    = (const float*)d_in[7];
    const float* bv    = (const float*)d_in[8];
    const float* Wo    = (const float*)d_in[9];
    const float* bo    = (const float*)d_in[10];
    const float* gamma = (const float*)d_in[11];
    const float* beta  = (const float*)d_in[12];
    const float* temp  = (const float*)d_in[13];

    float* out  = (float*)d_out;
    float* attn = out + (size_t)MROWS * HIDDEN;

    __nv_bfloat16 *Wqh, *Wql, *Wkh, *Wkl, *Wvh, *Woh;
    __nv_bfloat16 *Xqh, *Xql, *Xkh, *Xkl, *Xvh;
    __nv_bfloat16 *Qhp, *Qlp, *Khp, *Klp, *Vhp, *ctxp;
    float *projp, *invp;
    cudaGetSymbolAddress((void**)&Wqh, g_Wqh); cudaGetSymbolAddress((void**)&Wql, g_Wql);
    cudaGetSymbolAddress((void**)&Wkh, g_Wkh); cudaGetSymbolAddress((void**)&Wkl, g_Wkl);
    cudaGetSymbolAddress((void**)&Wvh, g_Wvh); cudaGetSymbolAddress((void**)&Woh, g_Woh);
    cudaGetSymbolAddress((void**)&Xqh, g_Xqh); cudaGetSymbolAddress((void**)&Xql, g_Xql);
    cudaGetSymbolAddress((void**)&Xkh, g_Xkh); cudaGetSymbolAddress((void**)&Xkl, g_Xkl);
    cudaGetSymbolAddress((void**)&Xvh, g_Xvh);
    cudaGetSymbolAddress((void**)&Qhp, g_Qh);  cudaGetSymbolAddress((void**)&Qlp, g_Ql);
    cudaGetSymbolAddress((void**)&Khp, g_Kh);  cudaGetSymbolAddress((void**)&Klp, g_Kl);
    cudaGetSymbolAddress((void**)&Vhp, g_Vh);
    cudaGetSymbolAddress((void**)&ctxp, g_ctx);
    cudaGetSymbolAddress((void**)&projp, g_proj);
    cudaGetSymbolAddress((void**)&invp, g_inv);

    cudaFuncSetAttribute(gemm_split_kernel,
                         cudaFuncAttributeMaxDynamicSharedMemorySize, GS_SMEM);
    cudaFuncSetAttribute(attn_pass1_kernel,
                         cudaFuncAttributeMaxDynamicSharedMemorySize, P1_SMEM);
    cudaFuncSetAttribute(attn_pass2_kernel,
                         cudaFuncAttributeMaxDynamicSharedMemorySize, P2_SMEM);

    // fused pre-split
    dim3 ps_grid(X4 / 256, 7);
    presplit_all<<<ps_grid, 256>>>(Wq, Wk, query, key, Wv, Wo, value,
                                   Wqh, Wql, Wkh, Wkl, Xqh, Xql, Xkh, Xkl,
                                   Wvh, Woh, Xvh);

    // projections
    dim3 pgrid(HIDDEN / 128, MROWS / 128);
    gemm_split_kernel<<<pgrid, 256, GS_SMEM>>>(Xqh, Xql, Wqh, Wql, bq, Qhp, Qlp);
    gemm_split_kernel<<<pgrid, 256, GS_SMEM>>>(Xkh, Xkl, Wkh, Wkl, bk, Khp, Klp);
    gemm_fast_kernel<<<pgrid, 256>>>(Xvh, Wvh, bv, Vhp, nullptr);

    // attention
    dim3 at_grid(SEQ / 128, NBATCH * HEADS);
    attn_pass1_kernel<<<at_grid, 512, P1_SMEM>>>(Qhp, Khp, Vhp, temp, invp, ctxp);
    attn_pass2_kernel<<<at_grid, 512, P2_SMEM>>>(Qhp, Qlp, Khp, Klp, temp, invp, attn);

    // output projection + LN
    gemm_fast_kernel<<<pgrid, 256>>>(ctxp, Woh, bo, nullptr, projp);
    ln_kernel<<<MROWS, 256>>>(projp, query, gamma, beta, out);
}

// round 10
// speedup vs baseline: 1.0891x; 1.0891x over previous
#include <cuda_runtime.h>
#include <cuda_bf16.h>
#include <math.h>

// ---------------------------------------------------------------------------
// CrossModalAttention, round 10: occupancy push (tcgen05 unavailable: ptxas
// targets compute_103 which rejects it — all tensor work stays on mma.sync).
//  - attn: q-tile 64, 256 threads, 93KB smem -> 2 CTAs/SM co-residency
//  - Q/K projections fused (grid.z), all GEMMs __launch_bounds__(256,2)
// ---------------------------------------------------------------------------

#define HIDDEN 1024
#define HEADS  16
#define DH     64
#define NBATCH 2
#define SEQ    2048
#define MROWS  (NBATCH * SEQ)   // 4096
#define LN_EPS 1e-5f

__device__ __nv_bfloat16 g_Wqh[HIDDEN * HIDDEN], g_Wql[HIDDEN * HIDDEN];
__device__ __nv_bfloat16 g_Wkh[HIDDEN * HIDDEN], g_Wkl[HIDDEN * HIDDEN];
__device__ __nv_bfloat16 g_Wvh[HIDDEN * HIDDEN], g_Woh[HIDDEN * HIDDEN];
__device__ __nv_bfloat16 g_Xqh[MROWS * HIDDEN], g_Xql[MROWS * HIDDEN];
__device__ __nv_bfloat16 g_Xkh[MROWS * HIDDEN], g_Xkl[MROWS * HIDDEN];
__device__ __nv_bfloat16 g_Xvh[MROWS * HIDDEN];
__device__ __nv_bfloat16 g_Qh[MROWS * HIDDEN], g_Ql[MROWS * HIDDEN];
__device__ __nv_bfloat16 g_Kh[MROWS * HIDDEN], g_Kl[MROWS * HIDDEN];
__device__ __nv_bfloat16 g_Vh[MROWS * HIDDEN];
__device__ __nv_bfloat16 g_ctx[MROWS * HIDDEN];
__device__ float g_proj[MROWS * HIDDEN];

// ---------------------------------------------------------------------------
// PTX helpers
// ---------------------------------------------------------------------------
__device__ __forceinline__ void mma_bf16(float* c, const unsigned* a, const unsigned* b) {
    asm volatile(
        "mma.sync.aligned.m16n8k16.row.col.f32.bf16.bf16.f32 "
        "{%0,%1,%2,%3}, {%4,%5,%6,%7}, {%8,%9}, {%0,%1,%2,%3};\n"
        : "+f"(c[0]), "+f"(c[1]), "+f"(c[2]), "+f"(c[3])
        : "r"(a[0]), "r"(a[1]), "r"(a[2]), "r"(a[3]), "r"(b[0]), "r"(b[1]));
}
__device__ __forceinline__ void ldsm_x4(unsigned* r, const __nv_bfloat16* p) {
    unsigned a = (unsigned)__cvta_generic_to_shared(p);
    asm volatile("ldmatrix.sync.aligned.m8n8.x4.shared.b16 {%0,%1,%2,%3}, [%4];\n"
                 : "=r"(r[0]), "=r"(r[1]), "=r"(r[2]), "=r"(r[3]) : "r"(a));
}
__device__ __forceinline__ void ldsm_x4t(unsigned* r, const __nv_bfloat16* p) {
    unsigned a = (unsigned)__cvta_generic_to_shared(p);
    asm volatile("ldmatrix.sync.aligned.m8n8.x4.trans.shared.b16 {%0,%1,%2,%3}, [%4];\n"
                 : "=r"(r[0]), "=r"(r[1]), "=r"(r[2]), "=r"(r[3]) : "r"(a));
}
#define CP_ASYNC16(dst, src) \
    asm volatile("cp.async.cg.shared.global [%0], [%1], 16;\n" :: "r"(dst), "l"(src))
#define CP_COMMIT() asm volatile("cp.async.commit_group;\n")
#define CP_WAIT(n)  asm volatile("cp.async.wait_group %0;\n" :: "n"(n))

__device__ __forceinline__ unsigned pack_bf2(float x, float y) {
    __nv_bfloat162 h = __float22bfloat162_rn(make_float2(x, y));
    return *(unsigned*)&h;
}
__device__ __forceinline__ void split_pair(float x, float y,
                                           __nv_bfloat162& hi, __nv_bfloat162& lo) {
    hi = __float22bfloat162_rn(make_float2(x, y));
    float2 hf = __bfloat1622float2(hi);
    lo = __float22bfloat162_rn(make_float2(x - hf.x, y - hf.y));
}

// ---------------------------------------------------------------------------
// presplit (fused, grid.y selects tensor)
// ---------------------------------------------------------------------------
#define W4 (HIDDEN * HIDDEN / 4)
#define X4 (MROWS * HIDDEN / 4)

__global__ void presplit_all(
    const float* __restrict__ Wq, const float* __restrict__ Wk,
    const float* __restrict__ q,  const float* __restrict__ k,
    const float* __restrict__ Wv, const float* __restrict__ Wo,
    const float* __restrict__ v,
    __nv_bfloat16* __restrict__ Wqh, __nv_bfloat16* __restrict__ Wql,
    __nv_bfloat16* __restrict__ Wkh, __nv_bfloat16* __restrict__ Wkl,
    __nv_bfloat16* __restrict__ Xqh, __nv_bfloat16* __restrict__ Xql,
    __nv_bfloat16* __restrict__ Xkh, __nv_bfloat16* __restrict__ Xkl,
    __nv_bfloat16* __restrict__ Wvh, __nv_bfloat16* __restrict__ Woh,
    __nv_bfloat16* __restrict__ Xvh) {
    const int z = blockIdx.y;
    const int i = blockIdx.x * blockDim.x + threadIdx.x;
    const float* src; __nv_bfloat16 *h, *l = nullptr; int n4;
    switch (z) {
        case 0: src = Wq; h = Wqh; l = Wql; n4 = W4; break;
        case 1: src = Wk; h = Wkh; l = Wkl; n4 = W4; break;
        case 2: src = q;  h = Xqh; l = Xql; n4 = X4; break;
        case 3: src = k;  h = Xkh; l = Xkl; n4 = X4; break;
        case 4: src = Wv; h = Wvh; n4 = W4; break;
        case 5: src = Wo; h = Woh; n4 = W4; break;
        default: src = v; h = Xvh; n4 = X4; break;
    }
    if (i >= n4) return;
    float4 val = ((const float4*)src)[i];
    if (l) {
        __nv_bfloat162 h0, l0, h1, l1;
        split_pair(val.x, val.y, h0, l0);
        split_pair(val.z, val.w, h1, l1);
        ((__nv_bfloat162*)h)[2 * i]     = h0;
        ((__nv_bfloat162*)h)[2 * i + 1] = h1;
        ((__nv_bfloat162*)l)[2 * i]     = l0;
        ((__nv_bfloat162*)l)[2 * i + 1] = l1;
    } else {
        ((__nv_bfloat162*)h)[2 * i]     = __float22bfloat162_rn(make_float2(val.x, val.y));
        ((__nv_bfloat162*)h)[2 * i + 1] = __float22bfloat162_rn(make_float2(val.z, val.w));
    }
}

// ---------------------------------------------------------------------------
// staging: 128 rows x 32 bf16 (row stride 40), 256 threads
// ---------------------------------------------------------------------------
__device__ __forceinline__ void stage_tile(unsigned smbase, const __nv_bfloat16* g, int t) {
#pragma unroll
    for (int r = 0; r < 2; ++r) {
        int idx = t + r * 256;
        int row = idx >> 2;
        int c8  = (idx & 3) * 8;
        CP_ASYNC16(smbase + (unsigned)(row * 40 + c8) * 2, g + (size_t)row * HIDDEN + c8);
    }
}

// B fragments via ldsm_x4
__device__ __forceinline__ void load_bfrag(unsigned bf[4][2], const __nv_bfloat16* B,
                                           int wn, int ks, int lane) {
#pragma unroll
    for (int jj = 0; jj < 2; ++jj) {
        unsigned r[4];
        int br = wn * 32 + jj * 16 + (lane & 15);
        int bc = ks + ((lane & 16) ? 8 : 0);
        ldsm_x4(r, &B[br * 40 + bc]);
        bf[2 * jj][0] = r[0]; bf[2 * jj][1] = r[2];
        bf[2 * jj + 1][0] = r[1]; bf[2 * jj + 1][1] = r[3];
    }
}

// ---------------------------------------------------------------------------
// gemm_split (Q and K fused via grid.z): 3-MMA, bf16 hi/lo out
// ---------------------------------------------------------------------------
#define GS_STAGE 10240
#define GS_SMEM  (8 * GS_STAGE)

__global__ __launch_bounds__(256, 2) void gemm_split_kernel(
    const __nv_bfloat16* __restrict__ A0g, const __nv_bfloat16* __restrict__ A1g,
    const __nv_bfloat16* __restrict__ L0g, const __nv_bfloat16* __restrict__ L1g,
    const __nv_bfloat16* __restrict__ W0g, const __nv_bfloat16* __restrict__ W1g,
    const __nv_bfloat16* __restrict__ V0g, const __nv_bfloat16* __restrict__ V1g,
    const float* __restrict__ b0g, const float* __restrict__ b1g,
    __nv_bfloat16* __restrict__ OH0g, __nv_bfloat16* __restrict__ OL0g,
    __nv_bfloat16* __restrict__ OH1g, __nv_bfloat16* __restrict__ OL1g) {
    extern __shared__ __align__(16) char sm[];
    const unsigned sb = (unsigned)__cvta_generic_to_shared(sm);

    const int z = blockIdx.z;
    const __nv_bfloat16* Ahg = z ? A1g : A0g;
    const __nv_bfloat16* Alg = z ? L1g : L0g;
    const __nv_bfloat16* Whg = z ? W1g : W0g;
    const __nv_bfloat16* Wlg = z ? V1g : V0g;
    const float* bias = z ? b1g : b0g;
    __nv_bfloat16* OH = z ? OH1g : OH0g;
    __nv_bfloat16* OL = z ? OL1g : OL0g;

    const int t = threadIdx.x, lane = t & 31, warp = t >> 5;
    const int wm = warp >> 2, wn = warp & 3;
    const int m0 = blockIdx.y * 128, n0 = blockIdx.x * 128;

    const __nv_bfloat16* Ah0 = Ahg + (size_t)m0 * HIDDEN;
    const __nv_bfloat16* Al0 = Alg + (size_t)m0 * HIDDEN;
    const __nv_bfloat16* Wh0 = Whg + (size_t)n0 * HIDDEN;
    const __nv_bfloat16* Wl0 = Wlg + (size_t)n0 * HIDDEN;

    float acc[4][4][4] = {};

    stage_tile(sb + 0 * GS_STAGE, Ah0, t);
    stage_tile(sb + 1 * GS_STAGE, Al0, t);
    stage_tile(sb + 2 * GS_STAGE, Wh0, t);
    stage_tile(sb + 3 * GS_STAGE, Wl0, t);
    CP_COMMIT();

    for (int i = 0; i < 32; ++i) {
        if (i < 31) {
            int k1 = (i + 1) * 32;
            unsigned s1 = sb + ((i + 1) & 1) * 4 * GS_STAGE;
            stage_tile(s1 + 0 * GS_STAGE, Ah0 + k1, t);
            stage_tile(s1 + 1 * GS_STAGE, Al0 + k1, t);
            stage_tile(s1 + 2 * GS_STAGE, Wh0 + k1, t);
            stage_tile(s1 + 3 * GS_STAGE, Wl0 + k1, t);
            CP_COMMIT();
            CP_WAIT(1);
        } else {
            CP_WAIT(0);
        }
        __syncthreads();

        char* base = sm + (i & 1) * 4 * GS_STAGE;
        const __nv_bfloat16* Ah = (const __nv_bfloat16*)(base);
        const __nv_bfloat16* Al = (const __nv_bfloat16*)(base + GS_STAGE);
        const __nv_bfloat16* Bh = (const __nv_bfloat16*)(base + 2 * GS_STAGE);
        const __nv_bfloat16* Bl = (const __nv_bfloat16*)(base + 3 * GS_STAGE);

#pragma unroll
        for (int ks = 0; ks < 32; ks += 16) {
            unsigned ah[4][4], al[4][4], bhf[4][2], blf[4][2];
            load_bfrag(bhf, Bh, wn, ks, lane);
            load_bfrag(blf, Bl, wn, ks, lane);
#pragma unroll
            for (int ii = 0; ii < 4; ++ii) {
                int ar = wm * 64 + ii * 16 + (lane & 15);
                int ac = ks + ((lane & 16) ? 8 : 0);
                ldsm_x4(ah[ii], &Ah[ar * 40 + ac]);
                ldsm_x4(al[ii], &Al[ar * 40 + ac]);
            }
#pragma unroll
            for (int ii = 0; ii < 4; ++ii)
#pragma unroll
                for (int j = 0; j < 4; ++j) {
                    mma_bf16(acc[ii][j], ah[ii], bhf[j]);
                    mma_bf16(acc[ii][j], ah[ii], blf[j]);
                    mma_bf16(acc[ii][j], al[ii], bhf[j]);
                }
        }
        __syncthreads();
    }

    const int g = lane >> 2, t2 = (lane & 3) * 2;
#pragma unroll
    for (int i = 0; i < 4; ++i) {
        int row = m0 + wm * 64 + i * 16 + g;
#pragma unroll
        for (int j = 0; j < 4; ++j) {
            int col = n0 + wn * 32 + j * 8 + t2;
            float bb0 = bias[col], bb1 = bias[col + 1];
            __nv_bfloat162 h2, l2;
            split_pair(acc[i][j][0] + bb0, acc[i][j][1] + bb1, h2, l2);
            *(__nv_bfloat162*)&OH[(size_t)row * HIDDEN + col] = h2;
            *(__nv_bfloat162*)&OL[(size_t)row * HIDDEN + col] = l2;
            split_pair(acc[i][j][2] + bb0, acc[i][j][3] + bb1, h2, l2);
            *(__nv_bfloat162*)&OH[(size_t)(row + 8) * HIDDEN + col] = h2;
            *(__nv_bfloat162*)&OL[(size_t)(row + 8) * HIDDEN + col] = l2;
        }
    }
}

// ---------------------------------------------------------------------------
// gemm_fast: 1-MMA, bf16 or fp32 out
// ---------------------------------------------------------------------------
__global__ __launch_bounds__(256, 2) void gemm_fast_kernel(
    const __nv_bfloat16* __restrict__ Ahg, const __nv_bfloat16* __restrict__ Whg,
    const float* __restrict__ bias,
    __nv_bfloat16* __restrict__ Obf, float* __restrict__ Of) {
    __shared__ __align__(16) __nv_bfloat16 smf[2][2][128 * 40];
    const int t = threadIdx.x, lane = t & 31, warp = t >> 5;
    const int wm = warp >> 2, wn = warp & 3;
    const int m0 = blockIdx.y * 128, n0 = blockIdx.x * 128;

    const __nv_bfloat16* A0 = Ahg + (size_t)m0 * HIDDEN;
    const __nv_bfloat16* W0 = Whg + (size_t)n0 * HIDDEN;

    float acc[4][4][4] = {};

    stage_tile((unsigned)__cvta_generic_to_shared(smf[0][0]), A0, t);
    stage_tile((unsigned)__cvta_generic_to_shared(smf[0][1]), W0, t);
    CP_COMMIT();

    for (int i = 0; i < 32; ++i) {
        if (i < 31) {
            int k1 = (i + 1) * 32;
            int s = (i + 1) & 1;
            stage_tile((unsigned)__cvta_generic_to_shared(smf[s][0]), A0 + k1, t);
            stage_tile((unsigned)__cvta_generic_to_shared(smf[s][1]), W0 + k1, t);
            CP_COMMIT();
            CP_WAIT(1);
        } else {
            CP_WAIT(0);
        }
        __syncthreads();

        const __nv_bfloat16* Ah = smf[i & 1][0];
        const __nv_bfloat16* Bh = smf[i & 1][1];

#pragma unroll
        for (int ks = 0; ks < 32; ks += 16) {
            unsigned ah[4][4], bhf[4][2];
            load_bfrag(bhf, Bh, wn, ks, lane);
#pragma unroll
            for (int ii = 0; ii < 4; ++ii) {
                int ar = wm * 64 + ii * 16 + (lane & 15);
                int ac = ks + ((lane & 16) ? 8 : 0);
                ldsm_x4(ah[ii], &Ah[ar * 40 + ac]);
            }
#pragma unroll
            for (int ii = 0; ii < 4; ++ii)
#pragma unroll
                for (int j = 0; j < 4; ++j)
                    mma_bf16(acc[ii][j], ah[ii], bhf[j]);
        }
        __syncthreads();
    }

    const int g = lane >> 2, t2 = (lane & 3) * 2;
    if (Of) {
#pragma unroll
        for (int i = 0; i < 4; ++i) {
            int row = m0 + wm * 64 + i * 16 + g;
#pragma unroll
            for (int j = 0; j < 4; ++j) {
                int col = n0 + wn * 32 + j * 8 + t2;
                float bb0 = bias[col], bb1 = bias[col + 1];
                *(float2*)&Of[(size_t)row * HIDDEN + col] =
                    make_float2(acc[i][j][0] + bb0, acc[i][j][1] + bb1);
                *(float2*)&Of[(size_t)(row + 8) * HIDDEN + col] =
                    make_float2(acc[i][j][2] + bb0, acc[i][j][3] + bb1);
            }
        }
    } else {
#pragma unroll
        for (int i = 0; i < 4; ++i) {
            int row = m0 + wm * 64 + i * 16 + g;
#pragma unroll
            for (int j = 0; j < 4; ++j) {
                int col = n0 + wn * 32 + j * 8 + t2;
                float bb0 = bias[col], bb1 = bias[col + 1];
                *(__nv_bfloat162*)&Obf[(size_t)row * HIDDEN + col] =
                    __float22bfloat162_rn(make_float2(acc[i][j][0] + bb0, acc[i][j][1] + bb1));
                *(__nv_bfloat162*)&Obf[(size_t)(row + 8) * HIDDEN + col] =
                    __float22bfloat162_rn(make_float2(acc[i][j][2] + bb0, acc[i][j][3] + bb1));
            }
        }
    }
}

// ---------------------------------------------------------------------------
// Fused attention: q-tile 64, 256 threads, 8 warps (wm 4 x wn 2).
// smem: QH 0(9216), QL 9216(9216),
//       K 18432 (pass1: 2x18432 K-hi; pass2: 2x36864 hi+lo),
//       V 55296 (pass1: 2x18432; interlude: red 64x66 f32),
//       PART 92160(512), INV 92672(256) -> 92928 total (2 CTAs/SM)
// ---------------------------------------------------------------------------
#define A_QH 0
#define A_QL 9216
#define A_K  18432
#define A_V  55296
#define A_PART 92160
#define A_INV  92672
#define A_SMEM 92928

// 64 rows x 64 cols (stride 72), 256 threads
__device__ __forceinline__ void stage_q64(unsigned sm, const __nv_bfloat16* g, int t) {
#pragma unroll
    for (int r = 0; r < 2; ++r) {
        int idx = t + r * 256;          // 0..511
        int row = idx >> 3;             // 0..63
        int c8  = (idx & 7) * 8;
        CP_ASYNC16(sm + (unsigned)(row * 72 + c8) * 2, g + (size_t)row * HIDDEN + c8);
    }
}
// 128 rows x 64 cols (stride 72), 256 threads
__device__ __forceinline__ void stage_k128(unsigned sm, const __nv_bfloat16* g, int t) {
#pragma unroll
    for (int r = 0; r < 4; ++r) {
        int idx = t + r * 256;          // 0..1023
        int row = idx >> 3;             // 0..127
        int c8  = (idx & 7) * 8;
        CP_ASYNC16(sm + (unsigned)(row * 72 + c8) * 2, g + (size_t)row * HIDDEN + c8);
    }
}

__global__ __launch_bounds__(256, 2) void attn_fused_kernel(
    const __nv_bfloat16* __restrict__ Qh, const __nv_bfloat16* __restrict__ Ql,
    const __nv_bfloat16* __restrict__ Kh, const __nv_bfloat16* __restrict__ Kl,
    const __nv_bfloat16* __restrict__ Vh,
    const float* __restrict__ temp,
    float* __restrict__ attn, __nv_bfloat16* __restrict__ ctx) {
    extern __shared__ __align__(16) char smraw[];
    __nv_bfloat16* q_h = (__nv_bfloat16*)(smraw + A_QH);
    __nv_bfloat16* q_l = (__nv_bfloat16*)(smraw + A_QL);
    float* red    = (float*)(smraw + A_V);
    float* part   = (float*)(smraw + A_PART);
    float* sm_inv = (float*)(smraw + A_INV);
    const unsigned sb = (unsigned)__cvta_generic_to_shared(smraw);

    const int t = threadIdx.x, lane = t & 31, wid = t >> 5;
    const int wm = wid >> 1, wn = wid & 1;          // wm 0..3, wn 0..1
    const int bh = blockIdx.y, b = bh >> 4, h = bh & 15;
    const int q0 = blockIdx.x * 64;
    const float ts = temp[0];
    const int g = lane >> 2, t2 = (lane & 3) * 2;
    const int lr = lane & 15, hc = (lane & 16) ? 8 : 0;

    const size_t qoff = (size_t)(b * SEQ + q0) * HIDDEN + h * DH;
    const size_t koff = (size_t)(b * SEQ) * HIDDEN + h * DH;

    // prologue: Q hi+lo (group 0), K0 hi + V0 (group 1)
    stage_q64(sb + A_QH, Qh + qoff, t);
    stage_q64(sb + A_QL, Ql + qoff, t);
    CP_COMMIT();
    stage_k128(sb + A_K, Kh + koff, t);
    stage_k128(sb + A_V, Vh + koff, t);
    CP_COMMIT();

    CP_WAIT(1);
    __syncthreads();
    unsigned aqh_f[4][4];
#pragma unroll
    for (int kd = 0; kd < 4; ++kd)
        ldsm_x4(aqh_f[kd], &q_h[(wm * 16 + lr) * 72 + kd * 16 + hc]);

    // ---------------- PASS 1: QK bf16 + exp + rowsum + PV (register P) ------
    float acc[8][4] = {};
    float rs0 = 0.f, rs1 = 0.f;

    for (int kt = 0; kt < 16; ++kt) {
        __syncthreads();
        if (kt < 15) {
            size_t go = (size_t)(kt + 1) * 128 * HIDDEN;
            stage_k128(sb + A_K + ((kt + 1) & 1) * 18432, Kh + koff + go, t);
            stage_k128(sb + A_V + ((kt + 1) & 1) * 18432, Vh + koff + go, t);
            CP_COMMIT();
            CP_WAIT(1);
        } else {
            CP_WAIT(0);
        }
        __syncthreads();

        const __nv_bfloat16* k_h = (const __nv_bfloat16*)(smraw + A_K + (kt & 1) * 18432);
        const __nv_bfloat16* v_h = (const __nv_bfloat16*)(smraw + A_V + (kt & 1) * 18432);

        float c[8][4] = {};
#pragma unroll
        for (int kd = 0; kd < 4; ++kd) {
#pragma unroll
            for (int jp = 0; jp < 4; ++jp) {
                unsigned bb[4];
                ldsm_x4(bb, &k_h[(wn * 64 + jp * 16 + lr) * 72 + kd * 16 + hc]);
                unsigned be[2] = {bb[0], bb[2]}, bo[2] = {bb[1], bb[3]};
                mma_bf16(c[2 * jp],     aqh_f[kd], be);
                mma_bf16(c[2 * jp + 1], aqh_f[kd], bo);
            }
        }

#pragma unroll
        for (int j = 0; j < 8; ++j) {
            c[j][0] = __expf(c[j][0] * ts);
            c[j][1] = __expf(c[j][1] * ts);
            c[j][2] = __expf(c[j][2] * ts);
            c[j][3] = __expf(c[j][3] * ts);
            rs0 += c[j][0] + c[j][1];
            rs1 += c[j][2] + c[j][3];
        }

#pragma unroll
        for (int j2 = 0; j2 < 4; ++j2) {
            unsigned ap[4];
            ap[0] = pack_bf2(c[2 * j2][0],     c[2 * j2][1]);
            ap[1] = pack_bf2(c[2 * j2][2],     c[2 * j2][3]);
            ap[2] = pack_bf2(c[2 * j2 + 1][0], c[2 * j2 + 1][1]);
            ap[3] = pack_bf2(c[2 * j2 + 1][2], c[2 * j2 + 1][3]);
#pragma unroll
            for (int djp = 0; djp < 4; ++djp) {
                unsigned bv[4];
                ldsm_x4t(bv, &v_h[(wn * 64 + j2 * 16 + lr) * 72 + djp * 16 + hc]);
                unsigned b0[2] = {bv[0], bv[1]}, b1[2] = {bv[2], bv[3]};
                mma_bf16(acc[2 * djp],     ap, b0);
                mma_bf16(acc[2 * djp + 1], ap, b1);
            }
        }
    }

    // rowsum reduce -> part[wn][64]
    rs0 += __shfl_xor_sync(0xffffffffu, rs0, 1);
    rs0 += __shfl_xor_sync(0xffffffffu, rs0, 2);
    rs1 += __shfl_xor_sync(0xffffffffu, rs1, 1);
    rs1 += __shfl_xor_sync(0xffffffffu, rs1, 2);
    if ((lane & 3) == 0) {
        part[wn * 64 + wm * 16 + g]     = rs0;
        part[wn * 64 + wm * 16 + g + 8] = rs1;
    }
    __syncthreads();

    // prefetch pass2 stage0 (K hi+lo into A_K..A_K+36864; red area untouched)
    stage_k128(sb + A_K,         Kh + koff, t);
    stage_k128(sb + A_K + 18432, Kl + koff, t);
    CP_COMMIT();

    if (t < 64)
        sm_inv[t] = 1.0f / (part[t] + part[64 + t]);

    // ctx reduction across wn (deterministic 2-step) into red[64][66]
    if (wn == 0) {
#pragma unroll
        for (int dj = 0; dj < 8; ++dj) {
            int r0 = wm * 16 + g, d = dj * 8 + t2;
            red[r0 * 66 + d]           = acc[dj][0];
            red[r0 * 66 + d + 1]       = acc[dj][1];
            red[(r0 + 8) * 66 + d]     = acc[dj][2];
            red[(r0 + 8) * 66 + d + 1] = acc[dj][3];
        }
    }
    __syncthreads();
    if (wn == 1) {
#pragma unroll
        for (int dj = 0; dj < 8; ++dj) {
            int r0 = wm * 16 + g, d = dj * 8 + t2;
            red[r0 * 66 + d]           += acc[dj][0];
            red[r0 * 66 + d + 1]       += acc[dj][1];
            red[(r0 + 8) * 66 + d]     += acc[dj][2];
            red[(r0 + 8) * 66 + d + 1] += acc[dj][3];
        }
    }
    __syncthreads();

    // ctx = red * inv (bf16): 64 rows x 64 cols, 256 threads
    {
        int row = t >> 2, d0 = (t & 3) * 16;
        float iv = sm_inv[row];
        size_t o = (size_t)(b * SEQ + q0 + row) * HIDDEN + h * DH + d0;
#pragma unroll
        for (int u = 0; u < 8; ++u) {
            float x = red[row * 66 + d0 + 2 * u]     * iv;
            float y = red[row * 66 + d0 + 2 * u + 1] * iv;
            *(__nv_bfloat162*)&ctx[o + 2 * u] =
                __float22bfloat162_rn(make_float2(x, y));
        }
    }

    // hoist Q-lo fragments (q_l untouched since prologue)
    unsigned aql_f[4][4];
#pragma unroll
    for (int kd = 0; kd < 4; ++kd)
        ldsm_x4(aql_f[kd], &q_l[(wm * 16 + lr) * 72 + kd * 16 + hc]);

    // ---------------- PASS 2: split-precision QK -> attn write --------------
    for (int kt = 0; kt < 16; ++kt) {
        __syncthreads();   // also guards red region before stage1 overwrite
        if (kt < 15) {
            size_t go = (size_t)(kt + 1) * 128 * HIDDEN;
            unsigned kb = sb + A_K + ((kt + 1) & 1) * 36864;
            stage_k128(kb,         Kh + koff + go, t);
            stage_k128(kb + 18432, Kl + koff + go, t);
            CP_COMMIT();
            CP_WAIT(1);
        } else {
            CP_WAIT(0);
        }
        __syncthreads();

        const __nv_bfloat16* k_h = (const __nv_bfloat16*)(smraw + A_K + (kt & 1) * 36864);
        const __nv_bfloat16* k_l = k_h + 9216;

        float c[8][4] = {};
#pragma unroll
        for (int kd = 0; kd < 4; ++kd) {
#pragma unroll
            for (int jp = 0; jp < 4; ++jp) {
                unsigned bh4[4], bl4[4];
                ldsm_x4(bh4, &k_h[(wn * 64 + jp * 16 + lr) * 72 + kd * 16 + hc]);
                ldsm_x4(bl4, &k_l[(wn * 64 + jp * 16 + lr) * 72 + kd * 16 + hc]);
                unsigned bhe[2] = {bh4[0], bh4[2]}, bho[2] = {bh4[1], bh4[3]};
                unsigned ble[2] = {bl4[0], bl4[2]}, blo[2] = {bl4[1], bl4[3]};
                mma_bf16(c[2 * jp], aqh_f[kd], bhe);
                mma_bf16(c[2 * jp], aqh_f[kd], ble);
                mma_bf16(c[2 * jp], aql_f[kd], bhe);
                mma_bf16(c[2 * jp + 1], aqh_f[kd], bho);
                mma_bf16(c[2 * jp + 1], aqh_f[kd], blo);
                mma_bf16(c[2 * jp + 1], aql_f[kd], bho);
            }
        }

        int rl = wm * 16 + g;
        float iv0 = sm_inv[rl], iv1 = sm_inv[rl + 8];
        size_t r0 = ((size_t)bh * SEQ + q0 + rl) * SEQ + (size_t)kt * 128 + wn * 64;
        size_t r1 = r0 + (size_t)8 * SEQ;
#pragma unroll
        for (int j = 0; j < 8; ++j) {
            float p0 = __expf(c[j][0] * ts) * iv0;
            float p1 = __expf(c[j][1] * ts) * iv0;
            float p2 = __expf(c[j][2] * ts) * iv1;
            float p3 = __expf(c[j][3] * ts) * iv1;
            int col = j * 8 + t2;
            *(float2*)&attn[r0 + col] = make_float2(p0, p1);
            *(float2*)&attn[r1 + col] = make_float2(p2, p3);
        }
    }
}

// ---------------------------------------------------------------------------
// LayerNorm(proj + query) -> out
// ---------------------------------------------------------------------------
__global__ void ln_kernel(const float* __restrict__ proj,
                          const float* __restrict__ query,
                          const float* __restrict__ gamma,
                          const float* __restrict__ beta,
                          float* __restrict__ out) {
    __shared__ float red[8];
    const size_t row = blockIdx.x;
    const int t = threadIdx.x;

    float x[4];
    float s = 0.f;
#pragma unroll
    for (int i = 0; i < 4; ++i) {
        int c = t + i * 256;
        x[i] = proj[row * HIDDEN + c] + query[row * HIDDEN + c];
        s += x[i];
    }
#pragma unroll
    for (int o = 16; o; o >>= 1) s += __shfl_xor_sync(0xffffffffu, s, o);
    if ((t & 31) == 0) red[t >> 5] = s;
    __syncthreads();
    s = red[0];
#pragma unroll
    for (int i = 1; i < 8; ++i) s += red[i];
    const float mu = s * (1.f / HIDDEN);

    float vs = 0.f;
#pragma unroll
    for (int i = 0; i < 4; ++i) { float d = x[i] - mu; vs += d * d; }
#pragma unroll
    for (int o = 16; o; o >>= 1) vs += __shfl_xor_sync(0xffffffffu, vs, o);
    __syncthreads();
    if ((t & 31) == 0) red[t >> 5] = vs;
    __syncthreads();
    vs = red[0];
#pragma unroll
    for (int i = 1; i < 8; ++i) vs += red[i];
    const float inv = rsqrtf(vs * (1.f / HIDDEN) + LN_EPS);

#pragma unroll
    for (int i = 0; i < 4; ++i) {
        int c = t + i * 256;
        out[row * HIDDEN + c] = (x[i] - mu) * inv * gamma[c] + beta[c];
    }
}

// ---------------------------------------------------------------------------
// Launch
// ---------------------------------------------------------------------------
extern "C" void kernel_launch(void* const* d_in, const int* in_sizes, int n_in,
                              void* d_out, int out_size) {
    const float* query = (const float*)d_in[0];
    const float* key   = (const float*)d_in[1];
    const float* value = (const float*)d_in[2];
    const float* Wq    = (const float*)d_in[3];
    const float* bq    = (const float*)d_in[4];
    const float* Wk    = (const float*)d_in[5];
    const float* bk    = (const float*)d_in[6];
    const float* Wv    = (const float*)d_in[7];
    const float* bv    = (const float*)d_in[8];
    const float* Wo    = (const float*)d_in[9];
    const float* bo    = (const float*)d_in[10];
    const float* gamma = (const float*)d_in[11];
    const float* beta  = (const float*)d_in[12];
    const float* temp  = (const float*)d_in[13];

    float* out  = (float*)d_out;
    float* attn = out + (size_t)MROWS * HIDDEN;

    __nv_bfloat16 *Wqh, *Wql, *Wkh, *Wkl, *Wvh, *Woh;
    __nv_bfloat16 *Xqh, *Xql, *Xkh, *Xkl, *Xvh;
    __nv_bfloat16 *Qhp, *Qlp, *Khp, *Klp, *Vhp, *ctxp;
    float *projp;
    cudaGetSymbolAddress((void**)&Wqh, g_Wqh); cudaGetSymbolAddress((void**)&Wql, g_Wql);
    cudaGetSymbolAddress((void**)&Wkh, g_Wkh); cudaGetSymbolAddress((void**)&Wkl, g_Wkl);
    cudaGetSymbolAddress((void**)&Wvh, g_Wvh); cudaGetSymbolAddress((void**)&Woh, g_Woh);
    cudaGetSymbolAddress((void**)&Xqh, g_Xqh); cudaGetSymbolAddress((void**)&Xql, g_Xql);
    cudaGetSymbolAddress((void**)&Xkh, g_Xkh); cudaGetSymbolAddress((void**)&Xkl, g_Xkl);
    cudaGetSymbolAddress((void**)&Xvh, g_Xvh);
    cudaGetSymbolAddress((void**)&Qhp, g_Qh);  cudaGetSymbolAddress((void**)&Qlp, g_Ql);
    cudaGetSymbolAddress((void**)&Khp, g_Kh);  cudaGetSymbolAddress((void**)&Klp, g_Kl);
    cudaGetSymbolAddress((void**)&Vhp, g_Vh);
    cudaGetSymbolAddress((void**)&ctxp, g_ctx);
    cudaGetSymbolAddress((void**)&projp, g_proj);

    cudaFuncSetAttribute(gemm_split_kernel,
                         cudaFuncAttributeMaxDynamicSharedMemorySize, GS_SMEM);
    cudaFuncSetAttribute(attn_fused_kernel,
                         cudaFuncAttributeMaxDynamicSharedMemorySize, A_SMEM);

    // fused pre-split
    dim3 ps_grid(X4 / 256, 7);
    presplit_all<<<ps_grid, 256>>>(Wq, Wk, query, key, Wv, Wo, value,
                                   Wqh, Wql, Wkh, Wkl, Xqh, Xql, Xkh, Xkl,
                                   Wvh, Woh, Xvh);

    // Q + K projections fused (grid.z), V projection
    dim3 qk_grid(HIDDEN / 128, MROWS / 128, 2);
    gemm_split_kernel<<<qk_grid, 256, GS_SMEM>>>(
        Xqh, Xkh, Xql, Xkl, Wqh, Wkh, Wql, Wkl, bq, bk,
        Qhp, Qlp, Khp, Klp);
    dim3 pgrid(HIDDEN / 128, MROWS / 128);
    gemm_fast_kernel<<<pgrid, 256>>>(Xvh, Wvh, bv, Vhp, nullptr);

    // fused attention (q-tile 64, 2 CTAs/SM)
    dim3 at_grid(SEQ / 64, NBATCH * HEADS);   // (32, 32)
    attn_fused_kernel<<<at_grid, 256, A_SMEM>>>(Qhp, Qlp, Khp, Klp, Vhp,
                                                temp, attn, ctxp);

    // output projection + LN
    gemm_fast_kernel<<<pgrid, 256>>>(ctxp, Woh, bo, nullptr, projp);
    ln_kernel<<<MROWS, 256>>>(projp, query, gamma, beta, out);
}

// round 11
// speedup vs baseline: 1.2931x; 1.1873x over previous
#include <cuda_runtime.h>
#include <cuda_bf16.h>
#include <math.h>

// ---------------------------------------------------------------------------
// CrossModalAttention, round 11: K-path precision truncation.
//  - attn pass2: S = (Qh+Ql)·Kh (2 MMAs; Kl never used -> deleted everywhere)
//  - K projection: 1-MMA bf16 (fused with V via grid.z)
//  - Q projection: 3-MMA split (unchanged); attn structure from round 10
// ---------------------------------------------------------------------------

#define HIDDEN 1024
#define HEADS  16
#define DH     64
#define NBATCH 2
#define SEQ    2048
#define MROWS  (NBATCH * SEQ)   // 4096
#define LN_EPS 1e-5f

__device__ __nv_bfloat16 g_Wqh[HIDDEN * HIDDEN], g_Wql[HIDDEN * HIDDEN];
__device__ __nv_bfloat16 g_Wkh[HIDDEN * HIDDEN];
__device__ __nv_bfloat16 g_Wvh[HIDDEN * HIDDEN], g_Woh[HIDDEN * HIDDEN];
__device__ __nv_bfloat16 g_Xqh[MROWS * HIDDEN], g_Xql[MROWS * HIDDEN];
__device__ __nv_bfloat16 g_Xkh[MROWS * HIDDEN];
__device__ __nv_bfloat16 g_Xvh[MROWS * HIDDEN];
__device__ __nv_bfloat16 g_Qh[MROWS * HIDDEN], g_Ql[MROWS * HIDDEN];
__device__ __nv_bfloat16 g_Kh[MROWS * HIDDEN];
__device__ __nv_bfloat16 g_Vh[MROWS * HIDDEN];
__device__ __nv_bfloat16 g_ctx[MROWS * HIDDEN];
__device__ float g_proj[MROWS * HIDDEN];

// ---------------------------------------------------------------------------
// PTX helpers
// ---------------------------------------------------------------------------
__device__ __forceinline__ void mma_bf16(float* c, const unsigned* a, const unsigned* b) {
    asm volatile(
        "mma.sync.aligned.m16n8k16.row.col.f32.bf16.bf16.f32 "
        "{%0,%1,%2,%3}, {%4,%5,%6,%7}, {%8,%9}, {%0,%1,%2,%3};\n"
        : "+f"(c[0]), "+f"(c[1]), "+f"(c[2]), "+f"(c[3])
        : "r"(a[0]), "r"(a[1]), "r"(a[2]), "r"(a[3]), "r"(b[0]), "r"(b[1]));
}
__device__ __forceinline__ void ldsm_x4(unsigned* r, const __nv_bfloat16* p) {
    unsigned a = (unsigned)__cvta_generic_to_shared(p);
    asm volatile("ldmatrix.sync.aligned.m8n8.x4.shared.b16 {%0,%1,%2,%3}, [%4];\n"
                 : "=r"(r[0]), "=r"(r[1]), "=r"(r[2]), "=r"(r[3]) : "r"(a));
}
__device__ __forceinline__ void ldsm_x4t(unsigned* r, const __nv_bfloat16* p) {
    unsigned a = (unsigned)__cvta_generic_to_shared(p);
    asm volatile("ldmatrix.sync.aligned.m8n8.x4.trans.shared.b16 {%0,%1,%2,%3}, [%4];\n"
                 : "=r"(r[0]), "=r"(r[1]), "=r"(r[2]), "=r"(r[3]) : "r"(a));
}
#define CP_ASYNC16(dst, src) \
    asm volatile("cp.async.cg.shared.global [%0], [%1], 16;\n" :: "r"(dst), "l"(src))
#define CP_COMMIT() asm volatile("cp.async.commit_group;\n")
#define CP_WAIT(n)  asm volatile("cp.async.wait_group %0;\n" :: "n"(n))

__device__ __forceinline__ unsigned pack_bf2(float x, float y) {
    __nv_bfloat162 h = __float22bfloat162_rn(make_float2(x, y));
    return *(unsigned*)&h;
}
__device__ __forceinline__ void split_pair(float x, float y,
                                           __nv_bfloat162& hi, __nv_bfloat162& lo) {
    hi = __float22bfloat162_rn(make_float2(x, y));
    float2 hf = __bfloat1622float2(hi);
    lo = __float22bfloat162_rn(make_float2(x - hf.x, y - hf.y));
}

// ---------------------------------------------------------------------------
// presplit (fused, grid.y selects tensor)
//  z=0 Wq(split) 1 q(split) 2 Wk(bf16) 3 k(bf16) 4 Wv 5 Wo 6 v
// ---------------------------------------------------------------------------
#define W4 (HIDDEN * HIDDEN / 4)
#define X4 (MROWS * HIDDEN / 4)

__global__ void presplit_all(
    const float* __restrict__ Wq, const float* __restrict__ q,
    const float* __restrict__ Wk, const float* __restrict__ k,
    const float* __restrict__ Wv, const float* __restrict__ Wo,
    const float* __restrict__ v,
    __nv_bfloat16* __restrict__ Wqh, __nv_bfloat16* __restrict__ Wql,
    __nv_bfloat16* __restrict__ Xqh, __nv_bfloat16* __restrict__ Xql,
    __nv_bfloat16* __restrict__ Wkh, __nv_bfloat16* __restrict__ Xkh,
    __nv_bfloat16* __restrict__ Wvh, __nv_bfloat16* __restrict__ Woh,
    __nv_bfloat16* __restrict__ Xvh) {
    const int z = blockIdx.y;
    const int i = blockIdx.x * blockDim.x + threadIdx.x;
    const float* src; __nv_bfloat16 *h, *l = nullptr; int n4;
    switch (z) {
        case 0: src = Wq; h = Wqh; l = Wql; n4 = W4; break;
        case 1: src = q;  h = Xqh; l = Xql; n4 = X4; break;
        case 2: src = Wk; h = Wkh; n4 = W4; break;
        case 3: src = k;  h = Xkh; n4 = X4; break;
        case 4: src = Wv; h = Wvh; n4 = W4; break;
        case 5: src = Wo; h = Woh; n4 = W4; break;
        default: src = v; h = Xvh; n4 = X4; break;
    }
    if (i >= n4) return;
    float4 val = ((const float4*)src)[i];
    if (l) {
        __nv_bfloat162 h0, l0, h1, l1;
        split_pair(val.x, val.y, h0, l0);
        split_pair(val.z, val.w, h1, l1);
        ((__nv_bfloat162*)h)[2 * i]     = h0;
        ((__nv_bfloat162*)h)[2 * i + 1] = h1;
        ((__nv_bfloat162*)l)[2 * i]     = l0;
        ((__nv_bfloat162*)l)[2 * i + 1] = l1;
    } else {
        ((__nv_bfloat162*)h)[2 * i]     = __float22bfloat162_rn(make_float2(val.x, val.y));
        ((__nv_bfloat162*)h)[2 * i + 1] = __float22bfloat162_rn(make_float2(val.z, val.w));
    }
}

// ---------------------------------------------------------------------------
// staging: 128 rows x 32 bf16 (row stride 40), 256 threads
// ---------------------------------------------------------------------------
__device__ __forceinline__ void stage_tile(unsigned smbase, const __nv_bfloat16* g, int t) {
#pragma unroll
    for (int r = 0; r < 2; ++r) {
        int idx = t + r * 256;
        int row = idx >> 2;
        int c8  = (idx & 3) * 8;
        CP_ASYNC16(smbase + (unsigned)(row * 40 + c8) * 2, g + (size_t)row * HIDDEN + c8);
    }
}

__device__ __forceinline__ void load_bfrag(unsigned bf[4][2], const __nv_bfloat16* B,
                                           int wn, int ks, int lane) {
#pragma unroll
    for (int jj = 0; jj < 2; ++jj) {
        unsigned r[4];
        int br = wn * 32 + jj * 16 + (lane & 15);
        int bc = ks + ((lane & 16) ? 8 : 0);
        ldsm_x4(r, &B[br * 40 + bc]);
        bf[2 * jj][0] = r[0]; bf[2 * jj][1] = r[2];
        bf[2 * jj + 1][0] = r[1]; bf[2 * jj + 1][1] = r[3];
    }
}

// ---------------------------------------------------------------------------
// gemm_split (Q only): 3-MMA, bf16 hi/lo out
// ---------------------------------------------------------------------------
#define GS_STAGE 10240
#define GS_SMEM  (8 * GS_STAGE)

__global__ __launch_bounds__(256, 2) void gemm_split_kernel(
    const __nv_bfloat16* __restrict__ Ahg, const __nv_bfloat16* __restrict__ Alg,
    const __nv_bfloat16* __restrict__ Whg, const __nv_bfloat16* __restrict__ Wlg,
    const float* __restrict__ bias,
    __nv_bfloat16* __restrict__ OH, __nv_bfloat16* __restrict__ OL) {
    extern __shared__ __align__(16) char sm[];
    const unsigned sb = (unsigned)__cvta_generic_to_shared(sm);

    const int t = threadIdx.x, lane = t & 31, warp = t >> 5;
    const int wm = warp >> 2, wn = warp & 3;
    const int m0 = blockIdx.y * 128, n0 = blockIdx.x * 128;

    const __nv_bfloat16* Ah0 = Ahg + (size_t)m0 * HIDDEN;
    const __nv_bfloat16* Al0 = Alg + (size_t)m0 * HIDDEN;
    const __nv_bfloat16* Wh0 = Whg + (size_t)n0 * HIDDEN;
    const __nv_bfloat16* Wl0 = Wlg + (size_t)n0 * HIDDEN;

    float acc[4][4][4] = {};

    stage_tile(sb + 0 * GS_STAGE, Ah0, t);
    stage_tile(sb + 1 * GS_STAGE, Al0, t);
    stage_tile(sb + 2 * GS_STAGE, Wh0, t);
    stage_tile(sb + 3 * GS_STAGE, Wl0, t);
    CP_COMMIT();

    for (int i = 0; i < 32; ++i) {
        if (i < 31) {
            int k1 = (i + 1) * 32;
            unsigned s1 = sb + ((i + 1) & 1) * 4 * GS_STAGE;
            stage_tile(s1 + 0 * GS_STAGE, Ah0 + k1, t);
            stage_tile(s1 + 1 * GS_STAGE, Al0 + k1, t);
            stage_tile(s1 + 2 * GS_STAGE, Wh0 + k1, t);
            stage_tile(s1 + 3 * GS_STAGE, Wl0 + k1, t);
            CP_COMMIT();
            CP_WAIT(1);
        } else {
            CP_WAIT(0);
        }
        __syncthreads();

        char* base = sm + (i & 1) * 4 * GS_STAGE;
        const __nv_bfloat16* Ah = (const __nv_bfloat16*)(base);
        const __nv_bfloat16* Al = (const __nv_bfloat16*)(base + GS_STAGE);
        const __nv_bfloat16* Bh = (const __nv_bfloat16*)(base + 2 * GS_STAGE);
        const __nv_bfloat16* Bl = (const __nv_bfloat16*)(base + 3 * GS_STAGE);

#pragma unroll
        for (int ks = 0; ks < 32; ks += 16) {
            unsigned ah[4][4], al[4][4], bhf[4][2], blf[4][2];
            load_bfrag(bhf, Bh, wn, ks, lane);
            load_bfrag(blf, Bl, wn, ks, lane);
#pragma unroll
            for (int ii = 0; ii < 4; ++ii) {
                int ar = wm * 64 + ii * 16 + (lane & 15);
                int ac = ks + ((lane & 16) ? 8 : 0);
                ldsm_x4(ah[ii], &Ah[ar * 40 + ac]);
                ldsm_x4(al[ii], &Al[ar * 40 + ac]);
            }
#pragma unroll
            for (int ii = 0; ii < 4; ++ii)
#pragma unroll
                for (int j = 0; j < 4; ++j) {
                    mma_bf16(acc[ii][j], ah[ii], bhf[j]);
                    mma_bf16(acc[ii][j], ah[ii], blf[j]);
                    mma_bf16(acc[ii][j], al[ii], bhf[j]);
                }
        }
        __syncthreads();
    }

    const int g = lane >> 2, t2 = (lane & 3) * 2;
#pragma unroll
    for (int i = 0; i < 4; ++i) {
        int row = m0 + wm * 64 + i * 16 + g;
#pragma unroll
        for (int j = 0; j < 4; ++j) {
            int col = n0 + wn * 32 + j * 8 + t2;
            float bb0 = bias[col], bb1 = bias[col + 1];
            __nv_bfloat162 h2, l2;
            split_pair(acc[i][j][0] + bb0, acc[i][j][1] + bb1, h2, l2);
            *(__nv_bfloat162*)&OH[(size_t)row * HIDDEN + col] = h2;
            *(__nv_bfloat162*)&OL[(size_t)row * HIDDEN + col] = l2;
            split_pair(acc[i][j][2] + bb0, acc[i][j][3] + bb1, h2, l2);
            *(__nv_bfloat162*)&OH[(size_t)(row + 8) * HIDDEN + col] = h2;
            *(__nv_bfloat162*)&OL[(size_t)(row + 8) * HIDDEN + col] = l2;
        }
    }
}

// ---------------------------------------------------------------------------
// gemm_fast: 1-MMA; grid.z selects (A,W,b,O) pair; fp32 out if Of set (z=0).
// ---------------------------------------------------------------------------
__global__ __launch_bounds__(256, 2) void gemm_fast_kernel(
    const __nv_bfloat16* __restrict__ A0g, const __nv_bfloat16* __restrict__ A1g,
    const __nv_bfloat16* __restrict__ W0g, const __nv_bfloat16* __restrict__ W1g,
    const float* __restrict__ b0g, const float* __restrict__ b1g,
    __nv_bfloat16* __restrict__ O0g, __nv_bfloat16* __restrict__ O1g,
    float* __restrict__ Of) {
    __shared__ __align__(16) __nv_bfloat16 smf[2][2][128 * 40];
    const int t = threadIdx.x, lane = t & 31, warp = t >> 5;
    const int wm = warp >> 2, wn = warp & 3;
    const int m0 = blockIdx.y * 128, n0 = blockIdx.x * 128;
    const int z = blockIdx.z;

    const __nv_bfloat16* A0 = (z ? A1g : A0g) + (size_t)m0 * HIDDEN;
    const __nv_bfloat16* W0 = (z ? W1g : W0g) + (size_t)n0 * HIDDEN;
    const float* bias = z ? b1g : b0g;
    __nv_bfloat16* Obf = z ? O1g : O0g;

    float acc[4][4][4] = {};

    stage_tile((unsigned)__cvta_generic_to_shared(smf[0][0]), A0, t);
    stage_tile((unsigned)__cvta_generic_to_shared(smf[0][1]), W0, t);
    CP_COMMIT();

    for (int i = 0; i < 32; ++i) {
        if (i < 31) {
            int k1 = (i + 1) * 32;
            int s = (i + 1) & 1;
            stage_tile((unsigned)__cvta_generic_to_shared(smf[s][0]), A0 + k1, t);
            stage_tile((unsigned)__cvta_generic_to_shared(smf[s][1]), W0 + k1, t);
            CP_COMMIT();
            CP_WAIT(1);
        } else {
            CP_WAIT(0);
        }
        __syncthreads();

        const __nv_bfloat16* Ah = smf[i & 1][0];
        const __nv_bfloat16* Bh = smf[i & 1][1];

#pragma unroll
        for (int ks = 0; ks < 32; ks += 16) {
            unsigned ah[4][4], bhf[4][2];
            load_bfrag(bhf, Bh, wn, ks, lane);
#pragma unroll
            for (int ii = 0; ii < 4; ++ii) {
                int ar = wm * 64 + ii * 16 + (lane & 15);
                int ac = ks + ((lane & 16) ? 8 : 0);
                ldsm_x4(ah[ii], &Ah[ar * 40 + ac]);
            }
#pragma unroll
            for (int ii = 0; ii < 4; ++ii)
#pragma unroll
                for (int j = 0; j < 4; ++j)
                    mma_bf16(acc[ii][j], ah[ii], bhf[j]);
        }
        __syncthreads();
    }

    const int g = lane >> 2, t2 = (lane & 3) * 2;
    if (Of) {
#pragma unroll
        for (int i = 0; i < 4; ++i) {
            int row = m0 + wm * 64 + i * 16 + g;
#pragma unroll
            for (int j = 0; j < 4; ++j) {
                int col = n0 + wn * 32 + j * 8 + t2;
                float bb0 = bias[col], bb1 = bias[col + 1];
                *(float2*)&Of[(size_t)row * HIDDEN + col] =
                    make_float2(acc[i][j][0] + bb0, acc[i][j][1] + bb1);
                *(float2*)&Of[(size_t)(row + 8) * HIDDEN + col] =
                    make_float2(acc[i][j][2] + bb0, acc[i][j][3] + bb1);
            }
        }
    } else {
#pragma unroll
        for (int i = 0; i < 4; ++i) {
            int row = m0 + wm * 64 + i * 16 + g;
#pragma unroll
            for (int j = 0; j < 4; ++j) {
                int col = n0 + wn * 32 + j * 8 + t2;
                float bb0 = bias[col], bb1 = bias[col + 1];
                *(__nv_bfloat162*)&Obf[(size_t)row * HIDDEN + col] =
                    __float22bfloat162_rn(make_float2(acc[i][j][0] + bb0, acc[i][j][1] + bb1));
                *(__nv_bfloat162*)&Obf[(size_t)(row + 8) * HIDDEN + col] =
                    __float22bfloat162_rn(make_float2(acc[i][j][2] + bb0, acc[i][j][3] + bb1));
            }
        }
    }
}

// ---------------------------------------------------------------------------
// Fused attention: q-tile 64, 256 threads, 8 warps (wm 4 x wn 2), 2 CTAs/SM.
// Pass2 S = (Qh+Ql)·Kh (2 MMAs) — Kl never used.
// smem: QH 0(9216), QL 9216(9216), K 18432(2x18432),
//       V 55296(2x18432, reused as red 64x66 f32), PART 92160(512),
//       INV 92672(256) -> 92928
// ---------------------------------------------------------------------------
#define A_QH 0
#define A_QL 9216
#define A_K  18432
#define A_V  55296
#define A_PART 92160
#define A_INV  92672
#define A_SMEM 92928

__device__ __forceinline__ void stage_q64(unsigned sm, const __nv_bfloat16* g, int t) {
#pragma unroll
    for (int r = 0; r < 2; ++r) {
        int idx = t + r * 256;
        int row = idx >> 3;
        int c8  = (idx & 7) * 8;
        CP_ASYNC16(sm + (unsigned)(row * 72 + c8) * 2, g + (size_t)row * HIDDEN + c8);
    }
}
__device__ __forceinline__ void stage_k128(unsigned sm, const __nv_bfloat16* g, int t) {
#pragma unroll
    for (int r = 0; r < 4; ++r) {
        int idx = t + r * 256;
        int row = idx >> 3;
        int c8  = (idx & 7) * 8;
        CP_ASYNC16(sm + (unsigned)(row * 72 + c8) * 2, g + (size_t)row * HIDDEN + c8);
    }
}

__global__ __launch_bounds__(256, 2) void attn_fused_kernel(
    const __nv_bfloat16* __restrict__ Qh, const __nv_bfloat16* __restrict__ Ql,
    const __nv_bfloat16* __restrict__ Kh,
    const __nv_bfloat16* __restrict__ Vh,
    const float* __restrict__ temp,
    float* __restrict__ attn, __nv_bfloat16* __restrict__ ctx) {
    extern __shared__ __align__(16) char smraw[];
    __nv_bfloat16* q_h = (__nv_bfloat16*)(smraw + A_QH);
    __nv_bfloat16* q_l = (__nv_bfloat16*)(smraw + A_QL);
    float* red    = (float*)(smraw + A_V);
    float* part   = (float*)(smraw + A_PART);
    float* sm_inv = (float*)(smraw + A_INV);
    const unsigned sb = (unsigned)__cvta_generic_to_shared(smraw);

    const int t = threadIdx.x, lane = t & 31, wid = t >> 5;
    const int wm = wid >> 1, wn = wid & 1;
    const int bh = blockIdx.y, b = bh >> 4, h = bh & 15;
    const int q0 = blockIdx.x * 64;
    const float ts = temp[0];
    const int g = lane >> 2, t2 = (lane & 3) * 2;
    const int lr = lane & 15, hc = (lane & 16) ? 8 : 0;

    const size_t qoff = (size_t)(b * SEQ + q0) * HIDDEN + h * DH;
    const size_t koff = (size_t)(b * SEQ) * HIDDEN + h * DH;

    // prologue: Q hi+lo (group 0), K0 + V0 (group 1)
    stage_q64(sb + A_QH, Qh + qoff, t);
    stage_q64(sb + A_QL, Ql + qoff, t);
    CP_COMMIT();
    stage_k128(sb + A_K, Kh + koff, t);
    stage_k128(sb + A_V, Vh + koff, t);
    CP_COMMIT();

    CP_WAIT(1);
    __syncthreads();
    unsigned aqh_f[4][4];
#pragma unroll
    for (int kd = 0; kd < 4; ++kd)
        ldsm_x4(aqh_f[kd], &q_h[(wm * 16 + lr) * 72 + kd * 16 + hc]);

    // ---------------- PASS 1: QK bf16 + exp + rowsum + PV (register P) ------
    float acc[8][4] = {};
    float rs0 = 0.f, rs1 = 0.f;

    for (int kt = 0; kt < 16; ++kt) {
        __syncthreads();
        if (kt < 15) {
            size_t go = (size_t)(kt + 1) * 128 * HIDDEN;
            stage_k128(sb + A_K + ((kt + 1) & 1) * 18432, Kh + koff + go, t);
            stage_k128(sb + A_V + ((kt + 1) & 1) * 18432, Vh + koff + go, t);
            CP_COMMIT();
            CP_WAIT(1);
        } else {
            CP_WAIT(0);
        }
        __syncthreads();

        const __nv_bfloat16* k_h = (const __nv_bfloat16*)(smraw + A_K + (kt & 1) * 18432);
        const __nv_bfloat16* v_h = (const __nv_bfloat16*)(smraw + A_V + (kt & 1) * 18432);

        float c[8][4] = {};
#pragma unroll
        for (int kd = 0; kd < 4; ++kd) {
#pragma unroll
            for (int jp = 0; jp < 4; ++jp) {
                unsigned bb[4];
                ldsm_x4(bb, &k_h[(wn * 64 + jp * 16 + lr) * 72 + kd * 16 + hc]);
                unsigned be[2] = {bb[0], bb[2]}, bo[2] = {bb[1], bb[3]};
                mma_bf16(c[2 * jp],     aqh_f[kd], be);
                mma_bf16(c[2 * jp + 1], aqh_f[kd], bo);
            }
        }

#pragma unroll
        for (int j = 0; j < 8; ++j) {
            c[j][0] = __expf(c[j][0] * ts);
            c[j][1] = __expf(c[j][1] * ts);
            c[j][2] = __expf(c[j][2] * ts);
            c[j][3] = __expf(c[j][3] * ts);
            rs0 += c[j][0] + c[j][1];
            rs1 += c[j][2] + c[j][3];
        }

#pragma unroll
        for (int j2 = 0; j2 < 4; ++j2) {
            unsigned ap[4];
            ap[0] = pack_bf2(c[2 * j2][0],     c[2 * j2][1]);
            ap[1] = pack_bf2(c[2 * j2][2],     c[2 * j2][3]);
            ap[2] = pack_bf2(c[2 * j2 + 1][0], c[2 * j2 + 1][1]);
            ap[3] = pack_bf2(c[2 * j2 + 1][2], c[2 * j2 + 1][3]);
#pragma unroll
            for (int djp = 0; djp < 4; ++djp) {
                unsigned bv[4];
                ldsm_x4t(bv, &v_h[(wn * 64 + j2 * 16 + lr) * 72 + djp * 16 + hc]);
                unsigned b0[2] = {bv[0], bv[1]}, b1[2] = {bv[2], bv[3]};
                mma_bf16(acc[2 * djp],     ap, b0);
                mma_bf16(acc[2 * djp + 1], ap, b1);
            }
        }
    }

    // rowsum reduce -> part[wn][64]
    rs0 += __shfl_xor_sync(0xffffffffu, rs0, 1);
    rs0 += __shfl_xor_sync(0xffffffffu, rs0, 2);
    rs1 += __shfl_xor_sync(0xffffffffu, rs1, 1);
    rs1 += __shfl_xor_sync(0xffffffffu, rs1, 2);
    if ((lane & 3) == 0) {
        part[wn * 64 + wm * 16 + g]     = rs0;
        part[wn * 64 + wm * 16 + g + 8] = rs1;
    }
    __syncthreads();

    // prefetch pass2 K0 into buffer 0
    stage_k128(sb + A_K, Kh + koff, t);
    CP_COMMIT();

    if (t < 64)
        sm_inv[t] = 1.0f / (part[t] + part[64 + t]);

    // ctx reduction across wn (deterministic 2-step) into red[64][66]
    if (wn == 0) {
#pragma unroll
        for (int dj = 0; dj < 8; ++dj) {
            int r0 = wm * 16 + g, d = dj * 8 + t2;
            red[r0 * 66 + d]           = acc[dj][0];
            red[r0 * 66 + d + 1]       = acc[dj][1];
            red[(r0 + 8) * 66 + d]     = acc[dj][2];
            red[(r0 + 8) * 66 + d + 1] = acc[dj][3];
        }
    }
    __syncthreads();
    if (wn == 1) {
#pragma unroll
        for (int dj = 0; dj < 8; ++dj) {
            int r0 = wm * 16 + g, d = dj * 8 + t2;
            red[r0 * 66 + d]           += acc[dj][0];
            red[r0 * 66 + d + 1]       += acc[dj][1];
            red[(r0 + 8) * 66 + d]     += acc[dj][2];
            red[(r0 + 8) * 66 + d + 1] += acc[dj][3];
        }
    }
    __syncthreads();

    // ctx = red * inv (bf16)
    {
        int row = t >> 2, d0 = (t & 3) * 16;
        float iv = sm_inv[row];
        size_t o = (size_t)(b * SEQ + q0 + row) * HIDDEN + h * DH + d0;
#pragma unroll
        for (int u = 0; u < 8; ++u) {
            float x = red[row * 66 + d0 + 2 * u]     * iv;
            float y = red[row * 66 + d0 + 2 * u + 1] * iv;
            *(__nv_bfloat162*)&ctx[o + 2 * u] =
                __float22bfloat162_rn(make_float2(x, y));
        }
    }

    // hoist Q-lo fragments (q_l untouched since prologue)
    unsigned aql_f[4][4];
#pragma unroll
    for (int kd = 0; kd < 4; ++kd)
        ldsm_x4(aql_f[kd], &q_l[(wm * 16 + lr) * 72 + kd * 16 + hc]);

    // ---------------- PASS 2: S = (Qh+Ql)·Kh -> attn write ------------------
    for (int kt = 0; kt < 16; ++kt) {
        __syncthreads();
        if (kt < 15) {
            size_t go = (size_t)(kt + 1) * 128 * HIDDEN;
            stage_k128(sb + A_K + ((kt + 1) & 1) * 18432, Kh + koff + go, t);
            CP_COMMIT();
            CP_WAIT(1);
        } else {
            CP_WAIT(0);
        }
        __syncthreads();

        const __nv_bfloat16* k_h = (const __nv_bfloat16*)(smraw + A_K + (kt & 1) * 18432);

        float c[8][4] = {};
#pragma unroll
        for (int kd = 0; kd < 4; ++kd) {
#pragma unroll
            for (int jp = 0; jp < 4; ++jp) {
                unsigned bb[4];
                ldsm_x4(bb, &k_h[(wn * 64 + jp * 16 + lr) * 72 + kd * 16 + hc]);
                unsigned be[2] = {bb[0], bb[2]}, bo[2] = {bb[1], bb[3]};
                mma_bf16(c[2 * jp],     aqh_f[kd], be);
                mma_bf16(c[2 * jp],     aql_f[kd], be);
                mma_bf16(c[2 * jp + 1], aqh_f[kd], bo);
                mma_bf16(c[2 * jp + 1], aql_f[kd], bo);
            }
        }

        int rl = wm * 16 + g;
        float iv0 = sm_inv[rl], iv1 = sm_inv[rl + 8];
        size_t r0 = ((size_t)bh * SEQ + q0 + rl) * SEQ + (size_t)kt * 128 + wn * 64;
        size_t r1 = r0 + (size_t)8 * SEQ;
#pragma unroll
        for (int j = 0; j < 8; ++j) {
            float p0 = __expf(c[j][0] * ts) * iv0;
            float p1 = __expf(c[j][1] * ts) * iv0;
            float p2 = __expf(c[j][2] * ts) * iv1;
            float p3 = __expf(c[j][3] * ts) * iv1;
            int col = j * 8 + t2;
            *(float2*)&attn[r0 + col] = make_float2(p0, p1);
            *(float2*)&attn[r1 + col] = make_float2(p2, p3);
        }
    }
}

// ---------------------------------------------------------------------------
// LayerNorm(proj + query) -> out
// ---------------------------------------------------------------------------
__global__ void ln_kernel(const float* __restrict__ proj,
                          const float* __restrict__ query,
                          const float* __restrict__ gamma,
                          const float* __restrict__ beta,
                          float* __restrict__ out) {
    __shared__ float red[8];
    const size_t row = blockIdx.x;
    const int t = threadIdx.x;

    float x[4];
    float s = 0.f;
#pragma unroll
    for (int i = 0; i < 4; ++i) {
        int c = t + i * 256;
        x[i] = proj[row * HIDDEN + c] + query[row * HIDDEN + c];
        s += x[i];
    }
#pragma unroll
    for (int o = 16; o; o >>= 1) s += __shfl_xor_sync(0xffffffffu, s, o);
    if ((t & 31) == 0) red[t >> 5] = s;
    __syncthreads();
    s = red[0];
#pragma unroll
    for (int i = 1; i < 8; ++i) s += red[i];
    const float mu = s * (1.f / HIDDEN);

    float vs = 0.f;
#pragma unroll
    for (int i = 0; i < 4; ++i) { float d = x[i] - mu; vs += d * d; }
#pragma unroll
    for (int o = 16; o; o >>= 1) vs += __shfl_xor_sync(0xffffffffu, vs, o);
    __syncthreads();
    if ((t & 31) == 0) red[t >> 5] = vs;
    __syncthreads();
    vs = red[0];
#pragma unroll
    for (int i = 1; i < 8; ++i) vs += red[i];
    const float inv = rsqrtf(vs * (1.f / HIDDEN) + LN_EPS);

#pragma unroll
    for (int i = 0; i < 4; ++i) {
        int c = t + i * 256;
        out[row * HIDDEN + c] = (x[i] - mu) * inv * gamma[c] + beta[c];
    }
}

// ---------------------------------------------------------------------------
// Launch
// ---------------------------------------------------------------------------
extern "C" void kernel_launch(void* const* d_in, const int* in_sizes, int n_in,
                              void* d_out, int out_size) {
    const float* query = (const float*)d_in[0];
    const float* key   = (const float*)d_in[1];
    const float* value = (const float*)d_in[2];
    const float* Wq    = (const float*)d_in[3];
    const float* bq    = (const float*)d_in[4];
    const float* Wk    = (const float*)d_in[5];
    const float* bk    = (const float*)d_in[6];
    const float* Wv    = (const float*)d_in[7];
    const float* bv    = (const float*)d_in[8];
    const float* Wo    = (const float*)d_in[9];
    const float* bo    = (const float*)d_in[10];
    const float* gamma = (const float*)d_in[11];
    const float* beta  = (const float*)d_in[12];
    const float* temp  = (const float*)d_in[13];

    float* out  = (float*)d_out;
    float* attn = out + (size_t)MROWS * HIDDEN;

    __nv_bfloat16 *Wqh, *Wql, *Wkh, *Wvh, *Woh;
    __nv_bfloat16 *Xqh, *Xql, *Xkh, *Xvh;
    __nv_bfloat16 *Qhp, *Qlp, *Khp, *Vhp, *ctxp;
    float *projp;
    cudaGetSymbolAddress((void**)&Wqh, g_Wqh); cudaGetSymbolAddress((void**)&Wql, g_Wql);
    cudaGetSymbolAddress((void**)&Wkh, g_Wkh);
    cudaGetSymbolAddress((void**)&Wvh, g_Wvh); cudaGetSymbolAddress((void**)&Woh, g_Woh);
    cudaGetSymbolAddress((void**)&Xqh, g_Xqh); cudaGetSymbolAddress((void**)&Xql, g_Xql);
    cudaGetSymbolAddress((void**)&Xkh, g_Xkh);
    cudaGetSymbolAddress((void**)&Xvh, g_Xvh);
    cudaGetSymbolAddress((void**)&Qhp, g_Qh);  cudaGetSymbolAddress((void**)&Qlp, g_Ql);
    cudaGetSymbolAddress((void**)&Khp, g_Kh);
    cudaGetSymbolAddress((void**)&Vhp, g_Vh);
    cudaGetSymbolAddress((void**)&ctxp, g_ctx);
    cudaGetSymbolAddress((void**)&projp, g_proj);

    cudaFuncSetAttribute(gemm_split_kernel,
                         cudaFuncAttributeMaxDynamicSharedMemorySize, GS_SMEM);
    cudaFuncSetAttribute(attn_fused_kernel,
                         cudaFuncAttributeMaxDynamicSharedMemorySize, A_SMEM);

    // fused pre-split
    dim3 ps_grid(X4 / 256, 7);
    presplit_all<<<ps_grid, 256>>>(Wq, query, Wk, key, Wv, Wo, value,
                                   Wqh, Wql, Xqh, Xql, Wkh, Xkh,
                                   Wvh, Woh, Xvh);

    // Q projection (split), K + V projections (fast, fused via grid.z)
    dim3 pgrid(HIDDEN / 128, MROWS / 128);
    gemm_split_kernel<<<pgrid, 256, GS_SMEM>>>(Xqh, Xql, Wqh, Wql, bq, Qhp, Qlp);
    dim3 kv_grid(HIDDEN / 128, MROWS / 128, 2);
    gemm_fast_kernel<<<kv_grid, 256>>>(Xkh, Xvh, Wkh, Wvh, bk, bv,
                                       Khp, Vhp, nullptr);

    // fused attention (q-tile 64, 2 CTAs/SM)
    dim3 at_grid(SEQ / 64, NBATCH * HEADS);   // (32, 32)
    attn_fused_kernel<<<at_grid, 256, A_SMEM>>>(Qhp, Qlp, Khp, Vhp,
                                                temp, attn, ctxp);

    // output projection + LN
    gemm_fast_kernel<<<pgrid, 256>>>(ctxp, ctxp, Woh, Woh, bo, bo,
                                     nullptr, nullptr, projp);
    ln_kernel<<<MROWS, 256>>>(projp, query, gamma, beta, out);
}